// round 1
// baseline (speedup 1.0000x reference)
#include <cuda_runtime.h>
#include <math.h>

#define N_TOK 4096
#define H_DIM 1024
#define F_DIM 4096
#define NE 8
#define CAP 1280   // min(max(4, ceil(2*1.25*4096/8)), 4096)

// ---------------- scratch (device globals; no allocations allowed) ----------------
__device__ float g_expert_in [(size_t)NE * CAP * H_DIM];   //  41.9 MB
__device__ float g_hmid      [(size_t)NE * CAP * F_DIM];   // 167.8 MB
__device__ float g_expert_out[(size_t)NE * CAP * H_DIM];   //  41.9 MB
__device__ float g_smid      [(size_t)N_TOK * F_DIM];      //  67.1 MB
__device__ int   g_e1[N_TOK];
__device__ int   g_e2[N_TOK];
__device__ int   g_slot1[N_TOK];
__device__ int   g_slot2[N_TOK];
__device__ float g_g1[N_TOK];
__device__ float g_g2[N_TOK];
__device__ int   g_cnt1[NE];
__device__ int   g_cnt2[NE];

// ---------------- routing ----------------
__global__ void zero_counts_kernel() {
    int t = threadIdx.x;
    if (t < NE) { g_cnt1[t] = 0; g_cnt2[t] = 0; }
}

// one block per token: logits = x[n] @ router_w, softmax, top-2
__global__ void router_kernel(const float* __restrict__ x, const float* __restrict__ rw) {
    int n = blockIdx.x;
    int tid = threadIdx.x;
    float acc[NE];
    #pragma unroll
    for (int e = 0; e < NE; e++) acc[e] = 0.f;
    const float* xr = x + (size_t)n * H_DIM;
    for (int h = tid; h < H_DIM; h += 256) {
        float xv = xr[h];
        const float* r = rw + h * NE;   // [H, E] row-major: 8 contiguous floats
        #pragma unroll
        for (int e = 0; e < NE; e++) acc[e] += xv * r[e];
    }
    __shared__ float red[NE][256];
    #pragma unroll
    for (int e = 0; e < NE; e++) red[e][tid] = acc[e];
    __syncthreads();
    for (int s = 128; s > 0; s >>= 1) {
        if (tid < s) {
            #pragma unroll
            for (int e = 0; e < NE; e++) red[e][tid] += red[e][tid + s];
        }
        __syncthreads();
    }
    if (tid == 0) {
        float l[NE], m = -1e30f;
        #pragma unroll
        for (int e = 0; e < NE; e++) { l[e] = red[e][0]; m = fmaxf(m, l[e]); }
        float p[NE], s = 0.f;
        #pragma unroll
        for (int e = 0; e < NE; e++) { p[e] = expf(l[e] - m); s += p[e]; }
        #pragma unroll
        for (int e = 0; e < NE; e++) p[e] /= s;
        int i1 = 0;
        #pragma unroll
        for (int e = 1; e < NE; e++) if (p[e] > p[i1]) i1 = e;   // first-max: matches jnp.argmax
        int i2 = -1; float best = -1.f;
        #pragma unroll
        for (int e = 0; e < NE; e++) if (e != i1 && p[e] > best) { best = p[e]; i2 = e; }
        g_e1[n] = i1; g_e2[n] = i2;
        g_g1[n] = p[i1]; g_g2[n] = p[i2];
    }
}

__global__ void assign1_kernel() {
    int n = blockIdx.x * 256 + threadIdx.x;
    if (n < N_TOK) g_slot1[n] = atomicAdd(&g_cnt1[g_e1[n]], 1);
}

// top-2 slots start after the (capped) top-1 block; also finalize combine weights
__global__ void assign2_kernel() {
    int n = blockIdx.x * 256 + threadIdx.x;
    if (n >= N_TOK) return;
    int e2 = g_e2[n];
    int off = min(g_cnt1[e2], CAP);
    int s2 = off + atomicAdd(&g_cnt2[e2], 1);
    g_slot2[n] = s2;
    float g1 = (g_slot1[n] < CAP) ? g_g1[n] : 0.f;
    float g2 = (s2 < CAP)         ? g_g2[n] : 0.f;
    float denom = fmaxf(g1 + g2, 1.1920929e-07f);   // fp32 eps, like jnp.finfo
    g_g1[n] = g1 / denom;
    g_g2[n] = g2 / denom;
}

// scatter token row into its (up to) two expert buffer slots
__global__ void dispatch_kernel(const float* __restrict__ x) {
    int n = blockIdx.x;
    const float4* xr = (const float4*)(x + (size_t)n * H_DIM);
    int e1 = g_e1[n], s1 = g_slot1[n];
    int e2 = g_e2[n], s2 = g_slot2[n];
    float4* d1 = (s1 < CAP) ? (float4*)(g_expert_in + ((size_t)e1 * CAP + s1) * H_DIM) : nullptr;
    float4* d2 = (s2 < CAP) ? (float4*)(g_expert_in + ((size_t)e2 * CAP + s2) * H_DIM) : nullptr;
    for (int i = threadIdx.x; i < H_DIM / 4; i += 256) {
        float4 v = xr[i];
        if (d1) d1[i] = v;
        if (d2) d2[i] = v;
    }
}

// ---------------- fp32 tiled GEMM: C = alpha * epi(A@B + bias) ----------------
// 128x128 tile, BK=8, 256 threads, 8x8 per thread. All shapes divide evenly.
__global__ __launch_bounds__(256) void gemm128_kernel(
    const float* __restrict__ A, const float* __restrict__ B,
    const float* __restrict__ bias, float* __restrict__ C,
    int Ncol, int K,
    long long strideA, long long strideB, long long strideBias, long long strideC,
    float alpha, int act)
{
    __shared__ float As[8][128];
    __shared__ float Bs[8][128];
    int e = blockIdx.z;
    A    += (long long)e * strideA;
    B    += (long long)e * strideB;
    bias += (long long)e * strideBias;
    C    += (long long)e * strideC;

    int bm = blockIdx.y * 128, bn = blockIdx.x * 128;
    int tid = threadIdx.x;
    int tx = tid & 15, ty = tid >> 4;

    int la_r = tid >> 1, la_c = (tid & 1) * 4;       // A tile: 128 rows x 8 cols
    int lb_r = tid >> 5, lb_c = (tid & 31) * 4;      // B tile: 8 rows x 128 cols

    const float* Aptr = A + (long long)(bm + la_r) * K + la_c;
    const float* Bptr = B + (long long)lb_r * Ncol + bn + lb_c;

    float acc[8][8];
    #pragma unroll
    for (int i = 0; i < 8; i++)
        #pragma unroll
        for (int j = 0; j < 8; j++) acc[i][j] = 0.f;

    for (int kk = 0; kk < K; kk += 8) {
        float4 av = *(const float4*)(Aptr + kk);
        float4 bv = *(const float4*)(Bptr + (long long)kk * Ncol);
        __syncthreads();
        As[la_c + 0][la_r] = av.x;
        As[la_c + 1][la_r] = av.y;
        As[la_c + 2][la_r] = av.z;
        As[la_c + 3][la_r] = av.w;
        *(float4*)&Bs[lb_r][lb_c] = bv;
        __syncthreads();
        #pragma unroll
        for (int k = 0; k < 8; k++) {
            float4 a0 = *(const float4*)&As[k][ty * 8];
            float4 a1 = *(const float4*)&As[k][ty * 8 + 4];
            float4 b0 = *(const float4*)&Bs[k][tx * 8];
            float4 b1 = *(const float4*)&Bs[k][tx * 8 + 4];
            float a[8] = {a0.x, a0.y, a0.z, a0.w, a1.x, a1.y, a1.z, a1.w};
            float b[8] = {b0.x, b0.y, b0.z, b0.w, b1.x, b1.y, b1.z, b1.w};
            #pragma unroll
            for (int i = 0; i < 8; i++)
                #pragma unroll
                for (int j = 0; j < 8; j++)
                    acc[i][j] = fmaf(a[i], b[j], acc[i][j]);
        }
    }

    #pragma unroll
    for (int i = 0; i < 8; i++) {
        long long row = bm + ty * 8 + i;
        #pragma unroll
        for (int j = 0; j < 8; j += 4) {
            int col = bn + tx * 8 + j;
            float4 v;
            v.x = acc[i][j + 0] + bias[col + 0];
            v.y = acc[i][j + 1] + bias[col + 1];
            v.z = acc[i][j + 2] + bias[col + 2];
            v.w = acc[i][j + 3] + bias[col + 3];
            if (act) {   // SiLU
                v.x = v.x / (1.f + expf(-v.x));
                v.y = v.y / (1.f + expf(-v.y));
                v.z = v.z / (1.f + expf(-v.z));
                v.w = v.w / (1.f + expf(-v.w));
            }
            v.x *= alpha; v.y *= alpha; v.z *= alpha; v.w *= alpha;
            *(float4*)&C[row * Ncol + col] = v;
        }
    }
}

// out[n] += g1*expert_out[e1,s1] + g2*expert_out[e2,s2]   (out already holds 0.1*shared)
__global__ void combine_kernel(float* __restrict__ out) {
    int n = blockIdx.x;
    int e1 = g_e1[n], s1 = g_slot1[n];
    int e2 = g_e2[n], s2 = g_slot2[n];
    float g1 = g_g1[n], g2 = g_g2[n];
    const float4* p1 = (s1 < CAP) ? (const float4*)(g_expert_out + ((size_t)e1 * CAP + s1) * H_DIM) : nullptr;
    const float4* p2 = (s2 < CAP) ? (const float4*)(g_expert_out + ((size_t)e2 * CAP + s2) * H_DIM) : nullptr;
    float4* o = (float4*)(out + (size_t)n * H_DIM);
    for (int i = threadIdx.x; i < H_DIM / 4; i += 256) {
        float4 v = o[i];
        if (p1) { float4 a = p1[i]; v.x += g1 * a.x; v.y += g1 * a.y; v.z += g1 * a.z; v.w += g1 * a.w; }
        if (p2) { float4 a = p2[i]; v.x += g2 * a.x; v.y += g2 * a.y; v.z += g2 * a.z; v.w += g2 * a.w; }
        o[i] = v;
    }
}

// ---------------- launcher ----------------
extern "C" void kernel_launch(void* const* d_in, const int* in_sizes, int n_in,
                              void* d_out, int out_size) {
    const float* x   = (const float*)d_in[0];
    const float* rw  = (const float*)d_in[1];
    const float* w1  = (const float*)d_in[2];
    const float* b1  = (const float*)d_in[3];
    const float* w2  = (const float*)d_in[4];
    const float* b2  = (const float*)d_in[5];
    const float* sw1 = (const float*)d_in[6];
    const float* sb1 = (const float*)d_in[7];
    const float* sw2 = (const float*)d_in[8];
    const float* sb2 = (const float*)d_in[9];
    float* out = (float*)d_out;

    float *expert_in, *hmid, *expert_out, *smid;
    cudaGetSymbolAddress((void**)&expert_in,  g_expert_in);
    cudaGetSymbolAddress((void**)&hmid,       g_hmid);
    cudaGetSymbolAddress((void**)&expert_out, g_expert_out);
    cudaGetSymbolAddress((void**)&smid,       g_smid);

    zero_counts_kernel<<<1, 32>>>();
    router_kernel<<<N_TOK, 256>>>(x, rw);
    assign1_kernel<<<N_TOK / 256, 256>>>();
    assign2_kernel<<<N_TOK / 256, 256>>>();
    dispatch_kernel<<<N_TOK, 256>>>(x);

    // expert GEMM1: [CAP,H] @ [H,F] -> silu -> hmid   (per expert)
    {
        dim3 grid(F_DIM / 128, CAP / 128, NE);
        gemm128_kernel<<<grid, 256>>>(expert_in, w1, b1, hmid, F_DIM, H_DIM,
            (long long)CAP * H_DIM, (long long)H_DIM * F_DIM, F_DIM, (long long)CAP * F_DIM,
            1.f, 1);
    }
    // expert GEMM2: [CAP,F] @ [F,H] + b2 -> expert_out
    {
        dim3 grid(H_DIM / 128, CAP / 128, NE);
        gemm128_kernel<<<grid, 256>>>(hmid, w2, b2, expert_out, H_DIM, F_DIM,
            (long long)CAP * F_DIM, (long long)F_DIM * H_DIM, H_DIM, (long long)CAP * H_DIM,
            1.f, 0);
    }
    // shared GEMM3: [N,H] @ [H,F] -> silu -> smid
    {
        dim3 grid(F_DIM / 128, N_TOK / 128, 1);
        gemm128_kernel<<<grid, 256>>>(x, sw1, sb1, smid, F_DIM, H_DIM,
            0, 0, 0, 0, 1.f, 1);
    }
    // shared GEMM4: 0.1 * ([N,F] @ [F,H] + sb2) -> out
    {
        dim3 grid(H_DIM / 128, N_TOK / 128, 1);
        gemm128_kernel<<<grid, 256>>>(smid, sw2, sb2, out, H_DIM, F_DIM,
            0, 0, 0, 0, 0.1f, 0);
    }
    combine_kernel<<<N_TOK, 256>>>(out);
}

// round 3
// speedup vs baseline: 1.9958x; 1.9958x over previous
#include <cuda_runtime.h>
#include <cuda_bf16.h>
#include <math.h>
#include <stdint.h>

#define N_TOK 4096
#define H_DIM 1024
#define F_DIM 4096
#define NE 8
#define CAP 1280   // min(max(4, ceil(2*1.25*4096/8)), 4096)

// ---------------- scratch (device globals; no allocations allowed) ----------------
__device__ float g_expert_in [(size_t)NE * CAP * H_DIM];
__device__ float g_hmid      [(size_t)NE * CAP * F_DIM];
__device__ float g_expert_out[(size_t)NE * CAP * H_DIM];
__device__ float g_smid      [(size_t)N_TOK * F_DIM];
__device__ int   g_e1[N_TOK];
__device__ int   g_e2[N_TOK];
__device__ int   g_slot1[N_TOK];
__device__ int   g_slot2[N_TOK];
__device__ float g_g1[N_TOK];
__device__ float g_g2[N_TOK];
__device__ int   g_cnt1[NE];
__device__ int   g_cnt2[NE];

// ---------------- GEMM tiling ----------------
#define BM 128
#define BN 128
#define BK 32
#define A_PITCH 40            // bf16 elems per A smem row (32 + 8 pad) -> 80B rows
#define B_PITCH 136           // bf16 elems per B smem row (128 + 8 pad) -> 272B rows
#define SA_BYTES (BM * A_PITCH * 2)          // 10240
#define SB_BYTES (BK * B_PITCH * 2)          // 8704
#define OFF_A_HI 0
#define OFF_A_LO SA_BYTES
#define OFF_B_HI (2 * SA_BYTES)
#define OFF_B_LO (2 * SA_BYTES + SB_BYTES)
#define STAGE_BYTES (2 * SA_BYTES + 2 * SB_BYTES)   // 37888
#define SM_TOTAL (2 * STAGE_BYTES)                  // 75776

__device__ __forceinline__ uint32_t smem_u32(const void* p) {
    uint32_t a;
    asm("{ .reg .u64 t; cvta.to.shared.u64 t, %1; cvt.u32.u64 %0, t; }" : "=r"(a) : "l"(p));
    return a;
}

#define LDSM_X4(r0, r1, r2, r3, addr) \
    asm volatile("ldmatrix.sync.aligned.m8n8.x4.shared.b16 {%0,%1,%2,%3}, [%4];" \
        : "=r"(r0), "=r"(r1), "=r"(r2), "=r"(r3) : "r"(addr))
#define LDSM_X4T(r0, r1, r2, r3, addr) \
    asm volatile("ldmatrix.sync.aligned.m8n8.x4.trans.shared.b16 {%0,%1,%2,%3}, [%4];" \
        : "=r"(r0), "=r"(r1), "=r"(r2), "=r"(r3) : "r"(addr))

__device__ __forceinline__ void mma16816(float* d, const uint32_t* a, const uint32_t* b) {
    asm volatile(
        "mma.sync.aligned.m16n8k16.row.col.f32.bf16.bf16.f32 "
        "{%0,%1,%2,%3}, {%4,%5,%6,%7}, {%8,%9}, {%0,%1,%2,%3};"
        : "+f"(d[0]), "+f"(d[1]), "+f"(d[2]), "+f"(d[3])
        : "r"(a[0]), "r"(a[1]), "r"(a[2]), "r"(a[3]), "r"(b[0]), "r"(b[1]));
}

// split fp32 pair -> packed bf16x2 hi and lo (residual)
__device__ __forceinline__ void split2(float a, float b, uint32_t& hi, uint32_t& lo) {
    __nv_bfloat16 ha = __float2bfloat16_rn(a), hb = __float2bfloat16_rn(b);
    float ra = a - __bfloat162float(ha);
    float rb = b - __bfloat162float(hb);
    unsigned short ua = *reinterpret_cast<unsigned short*>(&ha);
    unsigned short ub = *reinterpret_cast<unsigned short*>(&hb);
    hi = (uint32_t)ua | ((uint32_t)ub << 16);
    __nv_bfloat16 la = __float2bfloat16_rn(ra), lb = __float2bfloat16_rn(rb);
    unsigned short va = *reinterpret_cast<unsigned short*>(&la);
    unsigned short vb = *reinterpret_cast<unsigned short*>(&lb);
    lo = (uint32_t)va | ((uint32_t)vb << 16);
}

__device__ __forceinline__ void sts_a(char* smem, uint32_t stb, int f, float4 v) {
    int arow = f >> 3, ac4 = f & 7;
    uint32_t h0, l0, h1, l1;
    split2(v.x, v.y, h0, l0);
    split2(v.z, v.w, h1, l1);
    uint32_t off = (uint32_t)arow * (A_PITCH * 2) + (uint32_t)ac4 * 8;
    *(uint2*)(smem + stb + OFF_A_HI + off) = make_uint2(h0, h1);
    *(uint2*)(smem + stb + OFF_A_LO + off) = make_uint2(l0, l1);
}
__device__ __forceinline__ void sts_b(char* smem, uint32_t stb, int f, float4 v) {
    int brow = f >> 5, bc4 = f & 31;
    uint32_t h0, l0, h1, l1;
    split2(v.x, v.y, h0, l0);
    split2(v.z, v.w, h1, l1);
    uint32_t off = (uint32_t)brow * (B_PITCH * 2) + (uint32_t)bc4 * 8;
    *(uint2*)(smem + stb + OFF_B_HI + off) = make_uint2(h0, h1);
    *(uint2*)(smem + stb + OFF_B_LO + off) = make_uint2(l0, l1);
}

// ---------------- bf16x3 warp-MMA GEMM: C = alpha * epi(A@B + bias) ----------------
__global__ __launch_bounds__(256, 1) void gemm_tc_kernel(
    const float* __restrict__ A, const float* __restrict__ Bw,
    const float* __restrict__ bias, float* __restrict__ C,
    int Ncol, int K,
    long long sA, long long sB, long long sBias, long long sC,
    float alpha, int act)
{
    extern __shared__ char smem[];
    const int tid = threadIdx.x, w = tid >> 5, lane = tid & 31;
    const uint32_t sbase = smem_u32(smem);

    const int e = blockIdx.z;
    A    += (long long)e * sA;
    Bw   += (long long)e * sB;
    bias += (long long)e * sBias;
    C    += (long long)e * sC;
    const int bm = blockIdx.y * BM, bn = blockIdx.x * BN;

    const int wm = (w >> 2) * 64, wn = (w & 3) * 32;

    // lane-constant ldmatrix byte offsets (within a stage)
    const uint32_t aoff = (uint32_t)(wm + (lane & 15)) * (A_PITCH * 2) + ((lane >> 4) ? 16u : 0u);
    const uint32_t boff = (uint32_t)(lane & 15) * (B_PITCH * 2) + (uint32_t)(wn + (lane >> 4) * 8) * 2;

    float acc[4][4][4];
    #pragma unroll
    for (int i = 0; i < 4; i++)
        #pragma unroll
        for (int j = 0; j < 4; j++)
            #pragma unroll
            for (int kq = 0; kq < 4; kq++) acc[i][j][kq] = 0.f;

    const int S = K / BK;

    // --- load stage 0 directly ---
    #pragma unroll
    for (int i = 0; i < 4; i++) {
        int f = tid + i * 256;
        float4 va = *(const float4*)(A + (size_t)(bm + (f >> 3)) * K + (f & 7) * 4);
        sts_a(smem, 0, f, va);
        float4 vb = *(const float4*)(Bw + (size_t)(f >> 5) * Ncol + bn + (f & 31) * 4);
        sts_b(smem, 0, f, vb);
    }
    __syncthreads();

    for (int s = 0; s < S; s++) {
        const uint32_t stb = (uint32_t)(s & 1) * STAGE_BYTES;
        // prefetch next stage into registers
        float4 pa[4], pb[4];
        if (s + 1 < S) {
            const int k0 = (s + 1) * BK;
            #pragma unroll
            for (int i = 0; i < 4; i++) {
                int f = tid + i * 256;
                pa[i] = *(const float4*)(A + (size_t)(bm + (f >> 3)) * K + k0 + (f & 7) * 4);
                pb[i] = *(const float4*)(Bw + (size_t)(k0 + (f >> 5)) * Ncol + bn + (f & 31) * 4);
            }
        }
        // compute current stage
        #pragma unroll
        for (int ks = 0; ks < 2; ks++) {
            const int kb = ks * 16;
            uint32_t ah[4][4], al[4][4];
            #pragma unroll
            for (int mt = 0; mt < 4; mt++) {
                uint32_t ad = sbase + stb + aoff + (uint32_t)mt * (16 * A_PITCH * 2) + (uint32_t)kb * 2;
                LDSM_X4(ah[mt][0], ah[mt][1], ah[mt][2], ah[mt][3], ad + OFF_A_HI);
                LDSM_X4(al[mt][0], al[mt][1], al[mt][2], al[mt][3], ad + OFF_A_LO);
            }
            uint32_t bh[2][4], bl[2][4];
            #pragma unroll
            for (int np = 0; np < 2; np++) {
                uint32_t bd = sbase + stb + boff + (uint32_t)kb * (B_PITCH * 2) + (uint32_t)np * 32;
                LDSM_X4T(bh[np][0], bh[np][1], bh[np][2], bh[np][3], bd + OFF_B_HI);
                LDSM_X4T(bl[np][0], bl[np][1], bl[np][2], bl[np][3], bd + OFF_B_LO);
            }
            #pragma unroll
            for (int mt = 0; mt < 4; mt++) {
                #pragma unroll
                for (int nt = 0; nt < 4; nt++) {
                    uint32_t* ph = &bh[nt >> 1][(nt & 1) * 2];
                    uint32_t* pl = &bl[nt >> 1][(nt & 1) * 2];
                    mma16816(acc[mt][nt], ah[mt], ph);
                    mma16816(acc[mt][nt], ah[mt], pl);
                    mma16816(acc[mt][nt], al[mt], ph);
                }
            }
        }
        __syncthreads();
        if (s + 1 < S) {
            const uint32_t nstb = (uint32_t)((s + 1) & 1) * STAGE_BYTES;
            #pragma unroll
            for (int i = 0; i < 4; i++) {
                int f = tid + i * 256;
                sts_a(smem, nstb, f, pa[i]);
                sts_b(smem, nstb, f, pb[i]);
            }
            __syncthreads();
        }
    }

    // --- epilogue ---
    const int lr = lane >> 2, lc = (lane & 3) * 2;
    #pragma unroll
    for (int mt = 0; mt < 4; mt++) {
        #pragma unroll
        for (int nt = 0; nt < 4; nt++) {
            int col = bn + wn + nt * 8 + lc;
            float b0 = bias[col], b1 = bias[col + 1];
            #pragma unroll
            for (int half = 0; half < 2; half++) {
                int row = bm + wm + mt * 16 + lr + half * 8;
                float vx = acc[mt][nt][half * 2 + 0] + b0;
                float vy = acc[mt][nt][half * 2 + 1] + b1;
                if (act) {
                    vx = vx / (1.f + expf(-vx));
                    vy = vy / (1.f + expf(-vy));
                }
                vx *= alpha; vy *= alpha;
                *(float2*)(C + (size_t)row * Ncol + col) = make_float2(vx, vy);
            }
        }
    }
}

// ---------------- routing ----------------
__global__ void zero_counts_kernel() {
    int t = threadIdx.x;
    if (t < NE) { g_cnt1[t] = 0; g_cnt2[t] = 0; }
}

__global__ void router_kernel(const float* __restrict__ x, const float* __restrict__ rw) {
    int n = blockIdx.x;
    int tid = threadIdx.x;
    float acc[NE];
    #pragma unroll
    for (int e = 0; e < NE; e++) acc[e] = 0.f;
    const float* xr = x + (size_t)n * H_DIM;
    for (int h = tid; h < H_DIM; h += 256) {
        float xv = xr[h];
        const float* r = rw + h * NE;
        #pragma unroll
        for (int e = 0; e < NE; e++) acc[e] += xv * r[e];
    }
    __shared__ float red[NE][256];
    #pragma unroll
    for (int e = 0; e < NE; e++) red[e][tid] = acc[e];
    __syncthreads();
    for (int s = 128; s > 0; s >>= 1) {
        if (tid < s) {
            #pragma unroll
            for (int e = 0; e < NE; e++) red[e][tid] += red[e][tid + s];
        }
        __syncthreads();
    }
    if (tid == 0) {
        float l[NE], m = -1e30f;
        #pragma unroll
        for (int e = 0; e < NE; e++) { l[e] = red[e][0]; m = fmaxf(m, l[e]); }
        float p[NE], s = 0.f;
        #pragma unroll
        for (int e = 0; e < NE; e++) { p[e] = expf(l[e] - m); s += p[e]; }
        #pragma unroll
        for (int e = 0; e < NE; e++) p[e] /= s;
        int i1 = 0;
        #pragma unroll
        for (int e = 1; e < NE; e++) if (p[e] > p[i1]) i1 = e;
        int i2 = -1; float best = -1.f;
        #pragma unroll
        for (int e = 0; e < NE; e++) if (e != i1 && p[e] > best) { best = p[e]; i2 = e; }
        g_e1[n] = i1; g_e2[n] = i2;
        g_g1[n] = p[i1]; g_g2[n] = p[i2];
    }
}

__global__ void assign1_kernel() {
    int n = blockIdx.x * 256 + threadIdx.x;
    if (n < N_TOK) g_slot1[n] = atomicAdd(&g_cnt1[g_e1[n]], 1);
}

__global__ void assign2_kernel() {
    int n = blockIdx.x * 256 + threadIdx.x;
    if (n >= N_TOK) return;
    int e2 = g_e2[n];
    int off = min(g_cnt1[e2], CAP);
    int s2 = off + atomicAdd(&g_cnt2[e2], 1);
    g_slot2[n] = s2;
    float g1 = (g_slot1[n] < CAP) ? g_g1[n] : 0.f;
    float g2 = (s2 < CAP)         ? g_g2[n] : 0.f;
    float denom = fmaxf(g1 + g2, 1.1920929e-07f);
    g_g1[n] = g1 / denom;
    g_g2[n] = g2 / denom;
}

__global__ void dispatch_kernel(const float* __restrict__ x) {
    int n = blockIdx.x;
    const float4* xr = (const float4*)(x + (size_t)n * H_DIM);
    int e1 = g_e1[n], s1 = g_slot1[n];
    int e2 = g_e2[n], s2 = g_slot2[n];
    float4* d1 = (s1 < CAP) ? (float4*)(g_expert_in + ((size_t)e1 * CAP + s1) * H_DIM) : nullptr;
    float4* d2 = (s2 < CAP) ? (float4*)(g_expert_in + ((size_t)e2 * CAP + s2) * H_DIM) : nullptr;
    for (int i = threadIdx.x; i < H_DIM / 4; i += 256) {
        float4 v = xr[i];
        if (d1) d1[i] = v;
        if (d2) d2[i] = v;
    }
}

// zero expert_in slots beyond the filled counts
__global__ void zero_tail_kernel() {
    int r = blockIdx.x;            // 0 .. NE*CAP-1
    int e = r / CAP, s = r % CAP;
    int used = min(g_cnt1[e], CAP) + g_cnt2[e];
    if (s >= used) {
        float4* d = (float4*)(g_expert_in + (size_t)r * H_DIM);
        for (int i = threadIdx.x; i < H_DIM / 4; i += 128)
            d[i] = make_float4(0.f, 0.f, 0.f, 0.f);
    }
}

__global__ void combine_kernel(float* __restrict__ out) {
    int n = blockIdx.x;
    int e1 = g_e1[n], s1 = g_slot1[n];
    int e2 = g_e2[n], s2 = g_slot2[n];
    float g1 = g_g1[n], g2 = g_g2[n];
    const float4* p1 = (s1 < CAP) ? (const float4*)(g_expert_out + ((size_t)e1 * CAP + s1) * H_DIM) : nullptr;
    const float4* p2 = (s2 < CAP) ? (const float4*)(g_expert_out + ((size_t)e2 * CAP + s2) * H_DIM) : nullptr;
    float4* o = (float4*)(out + (size_t)n * H_DIM);
    for (int i = threadIdx.x; i < H_DIM / 4; i += 256) {
        float4 v = o[i];
        if (p1) { float4 a = p1[i]; v.x += g1 * a.x; v.y += g1 * a.y; v.z += g1 * a.z; v.w += g1 * a.w; }
        if (p2) { float4 a = p2[i]; v.x += g2 * a.x; v.y += g2 * a.y; v.z += g2 * a.z; v.w += g2 * a.w; }
        o[i] = v;
    }
}

// ---------------- launcher ----------------
extern "C" void kernel_launch(void* const* d_in, const int* in_sizes, int n_in,
                              void* d_out, int out_size) {
    const float* x   = (const float*)d_in[0];
    const float* rw  = (const float*)d_in[1];
    const float* w1  = (const float*)d_in[2];
    const float* b1  = (const float*)d_in[3];
    const float* w2  = (const float*)d_in[4];
    const float* b2  = (const float*)d_in[5];
    const float* sw1 = (const float*)d_in[6];
    const float* sb1 = (const float*)d_in[7];
    const float* sw2 = (const float*)d_in[8];
    const float* sb2 = (const float*)d_in[9];
    float* out = (float*)d_out;

    float *expert_in, *hmid, *expert_out, *smid;
    cudaGetSymbolAddress((void**)&expert_in,  g_expert_in);
    cudaGetSymbolAddress((void**)&hmid,       g_hmid);
    cudaGetSymbolAddress((void**)&expert_out, g_expert_out);
    cudaGetSymbolAddress((void**)&smid,       g_smid);

    cudaFuncSetAttribute(gemm_tc_kernel, cudaFuncAttributeMaxDynamicSharedMemorySize, SM_TOTAL);

    zero_counts_kernel<<<1, 32>>>();
    router_kernel<<<N_TOK, 256>>>(x, rw);
    assign1_kernel<<<N_TOK / 256, 256>>>();
    assign2_kernel<<<N_TOK / 256, 256>>>();
    dispatch_kernel<<<N_TOK, 256>>>(x);
    zero_tail_kernel<<<NE * CAP, 128>>>();

    // expert GEMM1: [CAP,H]@[H,F] -> silu -> hmid
    {
        dim3 grid(F_DIM / BN, CAP / BM, NE);
        gemm_tc_kernel<<<grid, 256, SM_TOTAL>>>(expert_in, w1, b1, hmid, F_DIM, H_DIM,
            (long long)CAP * H_DIM, (long long)H_DIM * F_DIM, F_DIM, (long long)CAP * F_DIM,
            1.f, 1);
    }
    // expert GEMM2: [CAP,F]@[F,H] + b2 -> expert_out
    {
        dim3 grid(H_DIM / BN, CAP / BM, NE);
        gemm_tc_kernel<<<grid, 256, SM_TOTAL>>>(hmid, w2, b2, expert_out, H_DIM, F_DIM,
            (long long)CAP * F_DIM, (long long)F_DIM * H_DIM, H_DIM, (long long)CAP * H_DIM,
            1.f, 0);
    }
    // shared GEMM3: [N,H]@[H,F] -> silu -> smid
    {
        dim3 grid(F_DIM / BN, N_TOK / BM, 1);
        gemm_tc_kernel<<<grid, 256, SM_TOTAL>>>(x, sw1, sb1, smid, F_DIM, H_DIM,
            0, 0, 0, 0, 1.f, 1);
    }
    // shared GEMM4: 0.1 * ([N,F]@[F,H] + sb2) -> out
    {
        dim3 grid(H_DIM / BN, N_TOK / BM, 1);
        gemm_tc_kernel<<<grid, 256, SM_TOTAL>>>(smid, sw2, sb2, out, H_DIM, F_DIM,
            0, 0, 0, 0, 0.1f, 0);
    }
    combine_kernel<<<N_TOK, 256>>>(out);
}

// round 4
// speedup vs baseline: 2.4735x; 1.2393x over previous
#include <cuda_runtime.h>
#include <cuda_bf16.h>
#include <math.h>
#include <stdint.h>

#define N_TOK 4096
#define H_DIM 1024
#define F_DIM 4096
#define NE 8
#define CAP 1280   // min(max(4, ceil(2*1.25*4096/8)), 4096)

// ---------------- scratch (device globals; no allocations allowed) ----------------
// bf16 hi/lo planes for all GEMM operands
__device__ __nv_bfloat16 g_w1h[(size_t)NE * H_DIM * F_DIM], g_w1l[(size_t)NE * H_DIM * F_DIM];
__device__ __nv_bfloat16 g_w2h[(size_t)NE * F_DIM * H_DIM], g_w2l[(size_t)NE * F_DIM * H_DIM];
__device__ __nv_bfloat16 g_sw1h[(size_t)H_DIM * F_DIM],     g_sw1l[(size_t)H_DIM * F_DIM];
__device__ __nv_bfloat16 g_sw2h[(size_t)F_DIM * H_DIM],     g_sw2l[(size_t)F_DIM * H_DIM];
__device__ __nv_bfloat16 g_xh [(size_t)N_TOK * H_DIM],      g_xl [(size_t)N_TOK * H_DIM];
__device__ __nv_bfloat16 g_eih[(size_t)NE * CAP * H_DIM],   g_eil[(size_t)NE * CAP * H_DIM];
__device__ __nv_bfloat16 g_hmh[(size_t)NE * CAP * F_DIM],   g_hml[(size_t)NE * CAP * F_DIM];
__device__ __nv_bfloat16 g_smh[(size_t)N_TOK * F_DIM],      g_sml[(size_t)N_TOK * F_DIM];
__device__ float g_expert_out[(size_t)NE * CAP * H_DIM];
__device__ int   g_e1[N_TOK];
__device__ int   g_e2[N_TOK];
__device__ int   g_slot1[N_TOK];
__device__ int   g_slot2[N_TOK];
__device__ float g_g1[N_TOK];
__device__ float g_g2[N_TOK];
__device__ int   g_cnt1[NE];
__device__ int   g_cnt2[NE];

// ---------------- helpers ----------------
__device__ __forceinline__ uint32_t smem_u32(const void* p) {
    uint32_t a;
    asm("{ .reg .u64 t; cvta.to.shared.u64 t, %1; cvt.u32.u64 %0, t; }" : "=r"(a) : "l"(p));
    return a;
}
#define LDSM_X4(r0, r1, r2, r3, addr) \
    asm volatile("ldmatrix.sync.aligned.m8n8.x4.shared.b16 {%0,%1,%2,%3}, [%4];" \
        : "=r"(r0), "=r"(r1), "=r"(r2), "=r"(r3) : "r"(addr))
#define LDSM_X4T(r0, r1, r2, r3, addr) \
    asm volatile("ldmatrix.sync.aligned.m8n8.x4.trans.shared.b16 {%0,%1,%2,%3}, [%4];" \
        : "=r"(r0), "=r"(r1), "=r"(r2), "=r"(r3) : "r"(addr))
__device__ __forceinline__ void mma16816(float* d, const uint32_t* a, const uint32_t* b) {
    asm volatile(
        "mma.sync.aligned.m16n8k16.row.col.f32.bf16.bf16.f32 "
        "{%0,%1,%2,%3}, {%4,%5,%6,%7}, {%8,%9}, {%0,%1,%2,%3};"
        : "+f"(d[0]), "+f"(d[1]), "+f"(d[2]), "+f"(d[3])
        : "r"(a[0]), "r"(a[1]), "r"(a[2]), "r"(a[3]), "r"(b[0]), "r"(b[1]));
}
__device__ __forceinline__ void cp16(uint32_t dst, const void* src) {
    asm volatile("cp.async.cg.shared.global [%0], [%1], 16;" :: "r"(dst), "l"(src));
}
#define CP_COMMIT() asm volatile("cp.async.commit_group;" ::: "memory")
#define CP_WAIT2()  asm volatile("cp.async.wait_group 2;" ::: "memory")

// split fp32 pair -> packed bf16x2 hi and lo (residual)
__device__ __forceinline__ void split2(float a, float b, uint32_t& hi, uint32_t& lo) {
    __nv_bfloat16 ha = __float2bfloat16_rn(a), hb = __float2bfloat16_rn(b);
    float ra = a - __bfloat162float(ha);
    float rb = b - __bfloat162float(hb);
    unsigned short ua = *reinterpret_cast<unsigned short*>(&ha);
    unsigned short ub = *reinterpret_cast<unsigned short*>(&hb);
    hi = (uint32_t)ua | ((uint32_t)ub << 16);
    __nv_bfloat16 la = __float2bfloat16_rn(ra), lb = __float2bfloat16_rn(rb);
    unsigned short va = *reinterpret_cast<unsigned short*>(&la);
    unsigned short vb = *reinterpret_cast<unsigned short*>(&lb);
    lo = (uint32_t)va | ((uint32_t)vb << 16);
}

// fp32 -> bf16 hi/lo planes (grid-stride over float4)
__global__ void convert_kernel(const float4* __restrict__ in,
                               uint2* __restrict__ hi, uint2* __restrict__ lo, int n4) {
    int i = blockIdx.x * 256 + threadIdx.x;
    int stride = gridDim.x * 256;
    for (; i < n4; i += stride) {
        float4 v = in[i];
        uint32_t h0, l0, h1, l1;
        split2(v.x, v.y, h0, l0);
        split2(v.z, v.w, h1, l1);
        hi[i] = make_uint2(h0, h1);
        lo[i] = make_uint2(l0, l1);
    }
}

// ---------------- GEMM tiling ----------------
#define BM 128
#define BN 128
#define BK 32
#define A_PITCH_B 80          // bytes per A smem row (32*2 + 16 pad)
#define B_PITCH_B 272         // bytes per B smem row (128*2 + 16 pad)
#define SA_BYTES (BM * A_PITCH_B)            // 10240
#define SB_BYTES (BK * B_PITCH_B)            // 8704
#define OFF_A_HI 0
#define OFF_A_LO SA_BYTES
#define OFF_B_HI (2 * SA_BYTES)
#define OFF_B_LO (2 * SA_BYTES + SB_BYTES)
#define STAGE_BYTES (2 * SA_BYTES + 2 * SB_BYTES)   // 37888
#define NSTAGE 4
#define SM_TOTAL (NSTAGE * STAGE_BYTES)             // 151552

// ---------------- bf16x3 warp-MMA GEMM with cp.async pipeline ----------------
// C = alpha * epi(A@B + bias); A,B given as bf16 hi/lo planes.
__global__ __launch_bounds__(256, 1) void gemm_tc_kernel(
    const __nv_bfloat16* __restrict__ Ahi, const __nv_bfloat16* __restrict__ Alo,
    const __nv_bfloat16* __restrict__ Bhi, const __nv_bfloat16* __restrict__ Blo,
    const float* __restrict__ bias,
    float* __restrict__ Cf, __nv_bfloat16* __restrict__ Chi, __nv_bfloat16* __restrict__ Clo,
    int Ncol, int K,
    long long sA, long long sB, long long sBias, long long sC,
    float alpha, int act, int out_bf16)
{
    extern __shared__ char smem[];
    const int tid = threadIdx.x, w = tid >> 5, lane = tid & 31;
    const uint32_t sbase = smem_u32(smem);

    const int e = blockIdx.z;
    Ahi += (long long)e * sA;  Alo += (long long)e * sA;
    Bhi += (long long)e * sB;  Blo += (long long)e * sB;
    bias += (long long)e * sBias;
    const long long coff = (long long)e * sC;
    const int bm = blockIdx.y * BM, bn = blockIdx.x * BN;

    const int wm = (w >> 2) * 64, wn = (w & 3) * 32;

    // per-thread cp.async source/dest mapping
    const int ra0 = tid >> 2,            ca = (tid & 3);         // A chunk (rows 0-63 for i=0)
    const int rb0 = tid >> 4,            cb = (tid & 15);        // B chunk (rows 0-15 for i=0)
    const uint32_t a_dst0 = (uint32_t)ra0 * A_PITCH_B + (uint32_t)ca * 16;
    const uint32_t b_dst0 = (uint32_t)rb0 * B_PITCH_B + (uint32_t)cb * 16;
    const __nv_bfloat16* aSh0 = Ahi + (size_t)(bm + ra0) * K + ca * 8;
    const __nv_bfloat16* aSl0 = Alo + (size_t)(bm + ra0) * K + ca * 8;
    const __nv_bfloat16* aSh1 = aSh0 + (size_t)64 * K;
    const __nv_bfloat16* aSl1 = aSl0 + (size_t)64 * K;
    const __nv_bfloat16* bSh0 = Bhi + (size_t)rb0 * Ncol + bn + cb * 8;
    const __nv_bfloat16* bSl0 = Blo + (size_t)rb0 * Ncol + bn + cb * 8;
    const __nv_bfloat16* bSh1 = bSh0 + (size_t)16 * Ncol;
    const __nv_bfloat16* bSl1 = bSl0 + (size_t)16 * Ncol;

    // lane-constant ldmatrix byte offsets (within a stage)
    const uint32_t aoff = (uint32_t)(wm + (lane & 15)) * A_PITCH_B + ((lane >> 4) ? 16u : 0u);
    const uint32_t boff = (uint32_t)(lane & 15) * B_PITCH_B + (uint32_t)(wn + (lane >> 4) * 8) * 2;

    float acc[4][4][4];
    #pragma unroll
    for (int i = 0; i < 4; i++)
        #pragma unroll
        for (int j = 0; j < 4; j++)
            #pragma unroll
            for (int kq = 0; kq < 4; kq++) acc[i][j][kq] = 0.f;

    const int S = K / BK;

    // prologue: issue 3 stages
    #pragma unroll
    for (int s = 0; s < NSTAGE - 1; s++) {
        const uint32_t stb = sbase + (uint32_t)s * STAGE_BYTES;
        const int k0 = s * BK;
        cp16(stb + OFF_A_HI + a_dst0,                        aSh0 + k0);
        cp16(stb + OFF_A_HI + a_dst0 + 64 * A_PITCH_B,       aSh1 + k0);
        cp16(stb + OFF_A_LO + a_dst0,                        aSl0 + k0);
        cp16(stb + OFF_A_LO + a_dst0 + 64 * A_PITCH_B,       aSl1 + k0);
        cp16(stb + OFF_B_HI + b_dst0,                        bSh0 + (size_t)k0 * Ncol);
        cp16(stb + OFF_B_HI + b_dst0 + 16 * B_PITCH_B,       bSh1 + (size_t)k0 * Ncol);
        cp16(stb + OFF_B_LO + b_dst0,                        bSl0 + (size_t)k0 * Ncol);
        cp16(stb + OFF_B_LO + b_dst0 + 16 * B_PITCH_B,       bSl1 + (size_t)k0 * Ncol);
        CP_COMMIT();
    }

    for (int s = 0; s < S; s++) {
        CP_WAIT2();
        __syncthreads();
        // issue loads for stage s+3 into buffer (s+3)%4
        if (s + NSTAGE - 1 < S) {
            const uint32_t stb = sbase + (uint32_t)((s + NSTAGE - 1) & (NSTAGE - 1)) * STAGE_BYTES;
            const int k0 = (s + NSTAGE - 1) * BK;
            cp16(stb + OFF_A_HI + a_dst0,                  aSh0 + k0);
            cp16(stb + OFF_A_HI + a_dst0 + 64 * A_PITCH_B, aSh1 + k0);
            cp16(stb + OFF_A_LO + a_dst0,                  aSl0 + k0);
            cp16(stb + OFF_A_LO + a_dst0 + 64 * A_PITCH_B, aSl1 + k0);
            cp16(stb + OFF_B_HI + b_dst0,                  bSh0 + (size_t)k0 * Ncol);
            cp16(stb + OFF_B_HI + b_dst0 + 16 * B_PITCH_B, bSh1 + (size_t)k0 * Ncol);
            cp16(stb + OFF_B_LO + b_dst0,                  bSl0 + (size_t)k0 * Ncol);
            cp16(stb + OFF_B_LO + b_dst0 + 16 * B_PITCH_B, bSl1 + (size_t)k0 * Ncol);
        }
        CP_COMMIT();
        // compute stage s
        const uint32_t stb = sbase + (uint32_t)(s & (NSTAGE - 1)) * STAGE_BYTES;
        #pragma unroll
        for (int ks = 0; ks < 2; ks++) {
            const int kb = ks * 16;
            uint32_t ah[4][4], al[4][4];
            #pragma unroll
            for (int mt = 0; mt < 4; mt++) {
                uint32_t ad = stb + aoff + (uint32_t)mt * (16 * A_PITCH_B) + (uint32_t)kb * 2;
                LDSM_X4(ah[mt][0], ah[mt][1], ah[mt][2], ah[mt][3], ad + OFF_A_HI);
                LDSM_X4(al[mt][0], al[mt][1], al[mt][2], al[mt][3], ad + OFF_A_LO);
            }
            uint32_t bh[2][4], bl[2][4];
            #pragma unroll
            for (int np = 0; np < 2; np++) {
                uint32_t bd = stb + boff + (uint32_t)kb * B_PITCH_B + (uint32_t)np * 32;
                LDSM_X4T(bh[np][0], bh[np][1], bh[np][2], bh[np][3], bd + OFF_B_HI);
                LDSM_X4T(bl[np][0], bl[np][1], bl[np][2], bl[np][3], bd + OFF_B_LO);
            }
            #pragma unroll
            for (int mt = 0; mt < 4; mt++) {
                #pragma unroll
                for (int nt = 0; nt < 4; nt++) {
                    uint32_t* ph = &bh[nt >> 1][(nt & 1) * 2];
                    uint32_t* pl = &bl[nt >> 1][(nt & 1) * 2];
                    mma16816(acc[mt][nt], ah[mt], ph);
                    mma16816(acc[mt][nt], ah[mt], pl);
                    mma16816(acc[mt][nt], al[mt], ph);
                }
            }
        }
    }

    // --- epilogue ---
    const int lr = lane >> 2, lc = (lane & 3) * 2;
    #pragma unroll
    for (int mt = 0; mt < 4; mt++) {
        #pragma unroll
        for (int nt = 0; nt < 4; nt++) {
            int col = bn + wn + nt * 8 + lc;
            float b0 = bias[col], b1 = bias[col + 1];
            #pragma unroll
            for (int half = 0; half < 2; half++) {
                long long row = bm + wm + mt * 16 + lr + half * 8;
                float vx = acc[mt][nt][half * 2 + 0] + b0;
                float vy = acc[mt][nt][half * 2 + 1] + b1;
                if (act) {
                    vx = vx / (1.f + expf(-vx));
                    vy = vy / (1.f + expf(-vy));
                }
                vx *= alpha; vy *= alpha;
                if (out_bf16) {
                    uint32_t h, l;
                    split2(vx, vy, h, l);
                    *(uint32_t*)(Chi + coff + row * Ncol + col) = h;
                    *(uint32_t*)(Clo + coff + row * Ncol + col) = l;
                } else {
                    *(float2*)(Cf + coff + row * Ncol + col) = make_float2(vx, vy);
                }
            }
        }
    }
}

// ---------------- routing ----------------
__global__ void zero_counts_kernel() {
    int t = threadIdx.x;
    if (t < NE) { g_cnt1[t] = 0; g_cnt2[t] = 0; }
}

__global__ void router_kernel(const float* __restrict__ x, const float* __restrict__ rw) {
    int n = blockIdx.x;
    int tid = threadIdx.x;
    float acc[NE];
    #pragma unroll
    for (int e = 0; e < NE; e++) acc[e] = 0.f;
    const float* xr = x + (size_t)n * H_DIM;
    for (int h = tid; h < H_DIM; h += 256) {
        float xv = xr[h];
        const float* r = rw + h * NE;
        #pragma unroll
        for (int e = 0; e < NE; e++) acc[e] += xv * r[e];
    }
    __shared__ float red[NE][256];
    #pragma unroll
    for (int e = 0; e < NE; e++) red[e][tid] = acc[e];
    __syncthreads();
    for (int s = 128; s > 0; s >>= 1) {
        if (tid < s) {
            #pragma unroll
            for (int e = 0; e < NE; e++) red[e][tid] += red[e][tid + s];
        }
        __syncthreads();
    }
    if (tid == 0) {
        float l[NE], m = -1e30f;
        #pragma unroll
        for (int e = 0; e < NE; e++) { l[e] = red[e][0]; m = fmaxf(m, l[e]); }
        float p[NE], s = 0.f;
        #pragma unroll
        for (int e = 0; e < NE; e++) { p[e] = expf(l[e] - m); s += p[e]; }
        #pragma unroll
        for (int e = 0; e < NE; e++) p[e] /= s;
        int i1 = 0;
        #pragma unroll
        for (int e = 1; e < NE; e++) if (p[e] > p[i1]) i1 = e;
        int i2 = -1; float best = -1.f;
        #pragma unroll
        for (int e = 0; e < NE; e++) if (e != i1 && p[e] > best) { best = p[e]; i2 = e; }
        g_e1[n] = i1; g_e2[n] = i2;
        g_g1[n] = p[i1]; g_g2[n] = p[i2];
    }
}

__global__ void assign1_kernel() {
    int n = blockIdx.x * 256 + threadIdx.x;
    if (n < N_TOK) g_slot1[n] = atomicAdd(&g_cnt1[g_e1[n]], 1);
}

__global__ void assign2_kernel() {
    int n = blockIdx.x * 256 + threadIdx.x;
    if (n >= N_TOK) return;
    int e2 = g_e2[n];
    int off = min(g_cnt1[e2], CAP);
    int s2 = off + atomicAdd(&g_cnt2[e2], 1);
    g_slot2[n] = s2;
    float g1 = (g_slot1[n] < CAP) ? g_g1[n] : 0.f;
    float g2 = (s2 < CAP)         ? g_g2[n] : 0.f;
    float denom = fmaxf(g1 + g2, 1.1920929e-07f);
    g_g1[n] = g1 / denom;
    g_g2[n] = g2 / denom;
}

// scatter token into expert buffers (bf16 hi/lo planes)
__global__ void dispatch_kernel(const float* __restrict__ x) {
    int n = blockIdx.x;
    const float4* xr = (const float4*)(x + (size_t)n * H_DIM);
    int e1 = g_e1[n], s1 = g_slot1[n];
    int e2 = g_e2[n], s2 = g_slot2[n];
    size_t r1 = ((size_t)e1 * CAP + s1) * H_DIM;
    size_t r2 = ((size_t)e2 * CAP + s2) * H_DIM;
    uint2* h1 = (s1 < CAP) ? (uint2*)(g_eih + r1) : nullptr;
    uint2* l1 = (s1 < CAP) ? (uint2*)(g_eil + r1) : nullptr;
    uint2* h2 = (s2 < CAP) ? (uint2*)(g_eih + r2) : nullptr;
    uint2* l2 = (s2 < CAP) ? (uint2*)(g_eil + r2) : nullptr;
    for (int i = threadIdx.x; i < H_DIM / 4; i += 256) {
        float4 v = xr[i];
        uint32_t ha, la, hb, lb;
        split2(v.x, v.y, ha, la);
        split2(v.z, v.w, hb, lb);
        uint2 hh = make_uint2(ha, hb), ll = make_uint2(la, lb);
        if (h1) { h1[i] = hh; l1[i] = ll; }
        if (h2) { h2[i] = hh; l2[i] = ll; }
    }
}

// zero expert_in slots beyond the filled counts
__global__ void zero_tail_kernel() {
    int r = blockIdx.x;            // 0 .. NE*CAP-1
    int e = r / CAP, s = r % CAP;
    int used = min(g_cnt1[e], CAP) + g_cnt2[e];
    if (s >= used) {
        uint4* dh = (uint4*)(g_eih + (size_t)r * H_DIM);
        uint4* dl = (uint4*)(g_eil + (size_t)r * H_DIM);
        for (int i = threadIdx.x; i < H_DIM / 8; i += 128) {
            dh[i] = make_uint4(0, 0, 0, 0);
            dl[i] = make_uint4(0, 0, 0, 0);
        }
    }
}

__global__ void combine_kernel(float* __restrict__ out) {
    int n = blockIdx.x;
    int e1 = g_e1[n], s1 = g_slot1[n];
    int e2 = g_e2[n], s2 = g_slot2[n];
    float g1 = g_g1[n], g2 = g_g2[n];
    const float4* p1 = (s1 < CAP) ? (const float4*)(g_expert_out + ((size_t)e1 * CAP + s1) * H_DIM) : nullptr;
    const float4* p2 = (s2 < CAP) ? (const float4*)(g_expert_out + ((size_t)e2 * CAP + s2) * H_DIM) : nullptr;
    float4* o = (float4*)(out + (size_t)n * H_DIM);
    for (int i = threadIdx.x; i < H_DIM / 4; i += 256) {
        float4 v = o[i];
        if (p1) { float4 a = p1[i]; v.x += g1 * a.x; v.y += g1 * a.y; v.z += g1 * a.z; v.w += g1 * a.w; }
        if (p2) { float4 a = p2[i]; v.x += g2 * a.x; v.y += g2 * a.y; v.z += g2 * a.z; v.w += g2 * a.w; }
        o[i] = v;
    }
}

// ---------------- launcher ----------------
extern "C" void kernel_launch(void* const* d_in, const int* in_sizes, int n_in,
                              void* d_out, int out_size) {
    const float* x   = (const float*)d_in[0];
    const float* rw  = (const float*)d_in[1];
    const float* w1  = (const float*)d_in[2];
    const float* b1  = (const float*)d_in[3];
    const float* w2  = (const float*)d_in[4];
    const float* b2  = (const float*)d_in[5];
    const float* sw1 = (const float*)d_in[6];
    const float* sb1 = (const float*)d_in[7];
    const float* sw2 = (const float*)d_in[8];
    const float* sb2 = (const float*)d_in[9];
    float* out = (float*)d_out;

    __nv_bfloat16 *w1h, *w1l, *w2h, *w2l, *sw1h, *sw1l, *sw2h, *sw2l;
    __nv_bfloat16 *xh, *xl, *eih, *eil, *hmh, *hml, *smh, *sml;
    float *expert_out;
    cudaGetSymbolAddress((void**)&w1h,  g_w1h);  cudaGetSymbolAddress((void**)&w1l,  g_w1l);
    cudaGetSymbolAddress((void**)&w2h,  g_w2h);  cudaGetSymbolAddress((void**)&w2l,  g_w2l);
    cudaGetSymbolAddress((void**)&sw1h, g_sw1h); cudaGetSymbolAddress((void**)&sw1l, g_sw1l);
    cudaGetSymbolAddress((void**)&sw2h, g_sw2h); cudaGetSymbolAddress((void**)&sw2l, g_sw2l);
    cudaGetSymbolAddress((void**)&xh,   g_xh);   cudaGetSymbolAddress((void**)&xl,   g_xl);
    cudaGetSymbolAddress((void**)&eih,  g_eih);  cudaGetSymbolAddress((void**)&eil,  g_eil);
    cudaGetSymbolAddress((void**)&hmh,  g_hmh);  cudaGetSymbolAddress((void**)&hml,  g_hml);
    cudaGetSymbolAddress((void**)&smh,  g_smh);  cudaGetSymbolAddress((void**)&sml,  g_sml);
    cudaGetSymbolAddress((void**)&expert_out, g_expert_out);

    cudaFuncSetAttribute(gemm_tc_kernel, cudaFuncAttributeMaxDynamicSharedMemorySize, SM_TOTAL);

    // preconvert weights + x to bf16 hi/lo
    convert_kernel<<<2048, 256>>>((const float4*)w1,  (uint2*)w1h,  (uint2*)w1l,  (int)((size_t)NE * H_DIM * F_DIM / 4));
    convert_kernel<<<2048, 256>>>((const float4*)w2,  (uint2*)w2h,  (uint2*)w2l,  (int)((size_t)NE * F_DIM * H_DIM / 4));
    convert_kernel<<<1024, 256>>>((const float4*)sw1, (uint2*)sw1h, (uint2*)sw1l, (int)((size_t)H_DIM * F_DIM / 4));
    convert_kernel<<<1024, 256>>>((const float4*)sw2, (uint2*)sw2h, (uint2*)sw2l, (int)((size_t)F_DIM * H_DIM / 4));
    convert_kernel<<<1024, 256>>>((const float4*)x,   (uint2*)xh,   (uint2*)xl,   (int)((size_t)N_TOK * H_DIM / 4));

    zero_counts_kernel<<<1, 32>>>();
    router_kernel<<<N_TOK, 256>>>(x, rw);
    assign1_kernel<<<N_TOK / 256, 256>>>();
    assign2_kernel<<<N_TOK / 256, 256>>>();
    dispatch_kernel<<<N_TOK, 256>>>(x);
    zero_tail_kernel<<<NE * CAP, 128>>>();

    // expert GEMM1: [CAP,H]@[H,F] -> silu -> hmid(bf16)
    {
        dim3 grid(F_DIM / BN, CAP / BM, NE);
        gemm_tc_kernel<<<grid, 256, SM_TOTAL>>>(eih, eil, w1h, w1l, b1,
            nullptr, hmh, hml, F_DIM, H_DIM,
            (long long)CAP * H_DIM, (long long)H_DIM * F_DIM, F_DIM, (long long)CAP * F_DIM,
            1.f, 1, 1);
    }
    // expert GEMM2: [CAP,F]@[F,H] + b2 -> expert_out(fp32)
    {
        dim3 grid(H_DIM / BN, CAP / BM, NE);
        gemm_tc_kernel<<<grid, 256, SM_TOTAL>>>(hmh, hml, w2h, w2l, b2,
            expert_out, nullptr, nullptr, H_DIM, F_DIM,
            (long long)CAP * F_DIM, (long long)F_DIM * H_DIM, H_DIM, (long long)CAP * H_DIM,
            1.f, 0, 0);
    }
    // shared GEMM3: [N,H]@[H,F] -> silu -> smid(bf16)
    {
        dim3 grid(F_DIM / BN, N_TOK / BM, 1);
        gemm_tc_kernel<<<grid, 256, SM_TOTAL>>>(xh, xl, sw1h, sw1l, sb1,
            nullptr, smh, sml, F_DIM, H_DIM,
            0, 0, 0, 0, 1.f, 1, 1);
    }
    // shared GEMM4: 0.1 * ([N,F]@[F,H] + sb2) -> out(fp32)
    {
        dim3 grid(H_DIM / BN, N_TOK / BM, 1);
        gemm_tc_kernel<<<grid, 256, SM_TOTAL>>>(smh, sml, sw2h, sw2l, sb2,
            out, nullptr, nullptr, H_DIM, F_DIM,
            0, 0, 0, 0, 0.1f, 0, 0);
    }
    combine_kernel<<<N_TOK, 256>>>(out);
}

// round 5
// speedup vs baseline: 2.7800x; 1.1239x over previous
#include <cuda_runtime.h>
#include <cuda_bf16.h>
#include <math.h>
#include <stdint.h>

#define N_TOK 4096
#define H_DIM 1024
#define F_DIM 4096
#define NE 8
#define CAP 1280   // min(max(4, ceil(2*1.25*4096/8)), 4096)

// ---------------- scratch (device globals; no allocations allowed) ----------------
__device__ __nv_bfloat16 g_w1h[(size_t)NE * H_DIM * F_DIM], g_w1l[(size_t)NE * H_DIM * F_DIM];
__device__ __nv_bfloat16 g_w2h[(size_t)NE * F_DIM * H_DIM], g_w2l[(size_t)NE * F_DIM * H_DIM];
__device__ __nv_bfloat16 g_sw1h[(size_t)H_DIM * F_DIM],     g_sw1l[(size_t)H_DIM * F_DIM];
__device__ __nv_bfloat16 g_sw2h[(size_t)F_DIM * H_DIM],     g_sw2l[(size_t)F_DIM * H_DIM];
__device__ __nv_bfloat16 g_xh [(size_t)N_TOK * H_DIM],      g_xl [(size_t)N_TOK * H_DIM];
__device__ __nv_bfloat16 g_eih[(size_t)NE * CAP * H_DIM],   g_eil[(size_t)NE * CAP * H_DIM];
__device__ __nv_bfloat16 g_hmh[(size_t)NE * CAP * F_DIM],   g_hml[(size_t)NE * CAP * F_DIM];
__device__ __nv_bfloat16 g_smh[(size_t)N_TOK * F_DIM],      g_sml[(size_t)N_TOK * F_DIM];
__device__ float g_expert_out[(size_t)NE * CAP * H_DIM];
__device__ int   g_e1[N_TOK];
__device__ int   g_e2[N_TOK];
__device__ int   g_slot1[N_TOK];
__device__ int   g_slot2[N_TOK];
__device__ float g_g1[N_TOK];
__device__ float g_g2[N_TOK];
__device__ int   g_cnt1[NE];
__device__ int   g_cnt2[NE];
__device__ int   g_used[NE];

// ---------------- helpers ----------------
__device__ __forceinline__ uint32_t smem_u32(const void* p) {
    uint32_t a;
    asm("{ .reg .u64 t; cvta.to.shared.u64 t, %1; cvt.u32.u64 %0, t; }" : "=r"(a) : "l"(p));
    return a;
}
#define LDSM_X4(r0, r1, r2, r3, addr) \
    asm volatile("ldmatrix.sync.aligned.m8n8.x4.shared.b16 {%0,%1,%2,%3}, [%4];" \
        : "=r"(r0), "=r"(r1), "=r"(r2), "=r"(r3) : "r"(addr))
#define LDSM_X4T(r0, r1, r2, r3, addr) \
    asm volatile("ldmatrix.sync.aligned.m8n8.x4.trans.shared.b16 {%0,%1,%2,%3}, [%4];" \
        : "=r"(r0), "=r"(r1), "=r"(r2), "=r"(r3) : "r"(addr))
__device__ __forceinline__ void mma16816(float* d, const uint32_t* a, const uint32_t* b) {
    asm volatile(
        "mma.sync.aligned.m16n8k16.row.col.f32.bf16.bf16.f32 "
        "{%0,%1,%2,%3}, {%4,%5,%6,%7}, {%8,%9}, {%0,%1,%2,%3};"
        : "+f"(d[0]), "+f"(d[1]), "+f"(d[2]), "+f"(d[3])
        : "r"(a[0]), "r"(a[1]), "r"(a[2]), "r"(a[3]), "r"(b[0]), "r"(b[1]));
}
__device__ __forceinline__ void cp16(uint32_t dst, const void* src) {
    asm volatile("cp.async.cg.shared.global [%0], [%1], 16;" :: "r"(dst), "l"(src));
}
#define CP_COMMIT() asm volatile("cp.async.commit_group;" ::: "memory")
#define CP_WAIT2()  asm volatile("cp.async.wait_group 2;" ::: "memory")

// split fp32 pair -> packed bf16x2 hi and lo (residual)
__device__ __forceinline__ void split2(float a, float b, uint32_t& hi, uint32_t& lo) {
    __nv_bfloat16 ha = __float2bfloat16_rn(a), hb = __float2bfloat16_rn(b);
    float ra = a - __bfloat162float(ha);
    float rb = b - __bfloat162float(hb);
    unsigned short ua = *reinterpret_cast<unsigned short*>(&ha);
    unsigned short ub = *reinterpret_cast<unsigned short*>(&hb);
    hi = (uint32_t)ua | ((uint32_t)ub << 16);
    __nv_bfloat16 la = __float2bfloat16_rn(ra), lb = __float2bfloat16_rn(rb);
    unsigned short va = *reinterpret_cast<unsigned short*>(&la);
    unsigned short vb = *reinterpret_cast<unsigned short*>(&lb);
    lo = (uint32_t)va | ((uint32_t)vb << 16);
}

// fp32 -> bf16 hi/lo planes: 8 elems per thread, exact grid, 16B stores per plane
__global__ __launch_bounds__(256) void convert_kernel(
    const float4* __restrict__ in, uint4* __restrict__ hi, uint4* __restrict__ lo) {
    int i = blockIdx.x * 256 + threadIdx.x;
    float4 v0 = in[i * 2];
    float4 v1 = in[i * 2 + 1];
    uint4 h, l;
    split2(v0.x, v0.y, h.x, l.x);
    split2(v0.z, v0.w, h.y, l.y);
    split2(v1.x, v1.y, h.z, l.z);
    split2(v1.z, v1.w, h.w, l.w);
    hi[i] = h;
    lo[i] = l;
}

// ---------------- GEMM tiling ----------------
#define BM 128
#define BN 128
#define BK 32
#define A_PITCH_B 80          // bytes per A smem row (32*2 + 16 pad)
#define B_PITCH_B 272         // bytes per B smem row (128*2 + 16 pad)
#define SA_BYTES (BM * A_PITCH_B)            // 10240
#define SB_BYTES (BK * B_PITCH_B)            // 8704
#define OFF_A_HI 0
#define OFF_A_LO SA_BYTES
#define OFF_B_HI (2 * SA_BYTES)
#define OFF_B_LO (2 * SA_BYTES + SB_BYTES)
#define STAGE_BYTES (2 * SA_BYTES + 2 * SB_BYTES)   // 37888
#define NSTAGE 4
#define SM_TOTAL (NSTAGE * STAGE_BYTES)             // 151552

// ---------------- bf16x3 warp-MMA GEMM with cp.async pipeline ----------------
__global__ __launch_bounds__(256, 1) void gemm_tc_kernel(
    const __nv_bfloat16* __restrict__ Ahi, const __nv_bfloat16* __restrict__ Alo,
    const __nv_bfloat16* __restrict__ Bhi, const __nv_bfloat16* __restrict__ Blo,
    const float* __restrict__ bias,
    float* __restrict__ Cf, __nv_bfloat16* __restrict__ Chi, __nv_bfloat16* __restrict__ Clo,
    int Ncol, int K,
    long long sA, long long sB, long long sBias, long long sC,
    float alpha, int act, int out_bf16, const int* __restrict__ used_arr)
{
    extern __shared__ char smem[];
    const int e = blockIdx.z;
    const int bm = blockIdx.y * BM, bn = blockIdx.x * BN;
    if (used_arr && bm >= used_arr[e]) return;   // skip fully-unused capacity tiles

    const int tid = threadIdx.x, w = tid >> 5, lane = tid & 31;
    const uint32_t sbase = smem_u32(smem);

    Ahi += (long long)e * sA;  Alo += (long long)e * sA;
    Bhi += (long long)e * sB;  Blo += (long long)e * sB;
    bias += (long long)e * sBias;
    const long long coff = (long long)e * sC;

    const int wm = (w >> 2) * 64, wn = (w & 3) * 32;

    const int ra0 = tid >> 2, ca = (tid & 3);
    const int rb0 = tid >> 4, cb = (tid & 15);
    const uint32_t a_dst0 = (uint32_t)ra0 * A_PITCH_B + (uint32_t)ca * 16;
    const uint32_t b_dst0 = (uint32_t)rb0 * B_PITCH_B + (uint32_t)cb * 16;
    const __nv_bfloat16* aSh0 = Ahi + (size_t)(bm + ra0) * K + ca * 8;
    const __nv_bfloat16* aSl0 = Alo + (size_t)(bm + ra0) * K + ca * 8;
    const __nv_bfloat16* aSh1 = aSh0 + (size_t)64 * K;
    const __nv_bfloat16* aSl1 = aSl0 + (size_t)64 * K;
    const __nv_bfloat16* bSh0 = Bhi + (size_t)rb0 * Ncol + bn + cb * 8;
    const __nv_bfloat16* bSl0 = Blo + (size_t)rb0 * Ncol + bn + cb * 8;
    const __nv_bfloat16* bSh1 = bSh0 + (size_t)16 * Ncol;
    const __nv_bfloat16* bSl1 = bSl0 + (size_t)16 * Ncol;

    const uint32_t aoff = (uint32_t)(wm + (lane & 15)) * A_PITCH_B + ((lane >> 4) ? 16u : 0u);
    const uint32_t boff = (uint32_t)(lane & 15) * B_PITCH_B + (uint32_t)(wn + (lane >> 4) * 8) * 2;

    float acc[4][4][4];
    #pragma unroll
    for (int i = 0; i < 4; i++)
        #pragma unroll
        for (int j = 0; j < 4; j++)
            #pragma unroll
            for (int kq = 0; kq < 4; kq++) acc[i][j][kq] = 0.f;

    const int S = K / BK;

    #pragma unroll
    for (int s = 0; s < NSTAGE - 1; s++) {
        const uint32_t stb = sbase + (uint32_t)s * STAGE_BYTES;
        const int k0 = s * BK;
        cp16(stb + OFF_A_HI + a_dst0,                  aSh0 + k0);
        cp16(stb + OFF_A_HI + a_dst0 + 64 * A_PITCH_B, aSh1 + k0);
        cp16(stb + OFF_A_LO + a_dst0,                  aSl0 + k0);
        cp16(stb + OFF_A_LO + a_dst0 + 64 * A_PITCH_B, aSl1 + k0);
        cp16(stb + OFF_B_HI + b_dst0,                  bSh0 + (size_t)k0 * Ncol);
        cp16(stb + OFF_B_HI + b_dst0 + 16 * B_PITCH_B, bSh1 + (size_t)k0 * Ncol);
        cp16(stb + OFF_B_LO + b_dst0,                  bSl0 + (size_t)k0 * Ncol);
        cp16(stb + OFF_B_LO + b_dst0 + 16 * B_PITCH_B, bSl1 + (size_t)k0 * Ncol);
        CP_COMMIT();
    }

    for (int s = 0; s < S; s++) {
        CP_WAIT2();
        __syncthreads();
        if (s + NSTAGE - 1 < S) {
            const uint32_t stb = sbase + (uint32_t)((s + NSTAGE - 1) & (NSTAGE - 1)) * STAGE_BYTES;
            const int k0 = (s + NSTAGE - 1) * BK;
            cp16(stb + OFF_A_HI + a_dst0,                  aSh0 + k0);
            cp16(stb + OFF_A_HI + a_dst0 + 64 * A_PITCH_B, aSh1 + k0);
            cp16(stb + OFF_A_LO + a_dst0,                  aSl0 + k0);
            cp16(stb + OFF_A_LO + a_dst0 + 64 * A_PITCH_B, aSl1 + k0);
            cp16(stb + OFF_B_HI + b_dst0,                  bSh0 + (size_t)k0 * Ncol);
            cp16(stb + OFF_B_HI + b_dst0 + 16 * B_PITCH_B, bSh1 + (size_t)k0 * Ncol);
            cp16(stb + OFF_B_LO + b_dst0,                  bSl0 + (size_t)k0 * Ncol);
            cp16(stb + OFF_B_LO + b_dst0 + 16 * B_PITCH_B, bSl1 + (size_t)k0 * Ncol);
        }
        CP_COMMIT();
        const uint32_t stb = sbase + (uint32_t)(s & (NSTAGE - 1)) * STAGE_BYTES;
        #pragma unroll
        for (int ks = 0; ks < 2; ks++) {
            const int kb = ks * 16;
            uint32_t ah[4][4], al[4][4];
            #pragma unroll
            for (int mt = 0; mt < 4; mt++) {
                uint32_t ad = stb + aoff + (uint32_t)mt * (16 * A_PITCH_B) + (uint32_t)kb * 2;
                LDSM_X4(ah[mt][0], ah[mt][1], ah[mt][2], ah[mt][3], ad + OFF_A_HI);
                LDSM_X4(al[mt][0], al[mt][1], al[mt][2], al[mt][3], ad + OFF_A_LO);
            }
            uint32_t bh[2][4], bl[2][4];
            #pragma unroll
            for (int np = 0; np < 2; np++) {
                uint32_t bd = stb + boff + (uint32_t)kb * B_PITCH_B + (uint32_t)np * 32;
                LDSM_X4T(bh[np][0], bh[np][1], bh[np][2], bh[np][3], bd + OFF_B_HI);
                LDSM_X4T(bl[np][0], bl[np][1], bl[np][2], bl[np][3], bd + OFF_B_LO);
            }
            #pragma unroll
            for (int mt = 0; mt < 4; mt++) {
                #pragma unroll
                for (int nt = 0; nt < 4; nt++) {
                    uint32_t* ph = &bh[nt >> 1][(nt & 1) * 2];
                    uint32_t* pl = &bl[nt >> 1][(nt & 1) * 2];
                    mma16816(acc[mt][nt], ah[mt], ph);
                    mma16816(acc[mt][nt], ah[mt], pl);
                    mma16816(acc[mt][nt], al[mt], ph);
                }
            }
        }
    }

    // --- epilogue ---
    const int lr = lane >> 2, lc = (lane & 3) * 2;
    #pragma unroll
    for (int mt = 0; mt < 4; mt++) {
        #pragma unroll
        for (int nt = 0; nt < 4; nt++) {
            int col = bn + wn + nt * 8 + lc;
            float b0 = bias[col], b1 = bias[col + 1];
            #pragma unroll
            for (int half = 0; half < 2; half++) {
                long long row = bm + wm + mt * 16 + lr + half * 8;
                float vx = acc[mt][nt][half * 2 + 0] + b0;
                float vy = acc[mt][nt][half * 2 + 1] + b1;
                if (act) {
                    vx = vx / (1.f + expf(-vx));
                    vy = vy / (1.f + expf(-vy));
                }
                vx *= alpha; vy *= alpha;
                if (out_bf16) {
                    uint32_t h, l;
                    split2(vx, vy, h, l);
                    *(uint32_t*)(Chi + coff + row * Ncol + col) = h;
                    *(uint32_t*)(Clo + coff + row * Ncol + col) = l;
                } else {
                    *(float2*)(Cf + coff + row * Ncol + col) = make_float2(vx, vy);
                }
            }
        }
    }
}

// ---------------- routing ----------------
__global__ void zero_counts_kernel() {
    int t = threadIdx.x;
    if (t < NE) { g_cnt1[t] = 0; g_cnt2[t] = 0; }
}

__global__ void router_kernel(const float* __restrict__ x, const float* __restrict__ rw) {
    int n = blockIdx.x;
    int tid = threadIdx.x;
    float acc[NE];
    #pragma unroll
    for (int e = 0; e < NE; e++) acc[e] = 0.f;
    const float* xr = x + (size_t)n * H_DIM;
    for (int h = tid; h < H_DIM; h += 256) {
        float xv = xr[h];
        const float* r = rw + h * NE;
        #pragma unroll
        for (int e = 0; e < NE; e++) acc[e] += xv * r[e];
    }
    __shared__ float red[NE][256];
    #pragma unroll
    for (int e = 0; e < NE; e++) red[e][tid] = acc[e];
    __syncthreads();
    for (int s = 128; s > 0; s >>= 1) {
        if (tid < s) {
            #pragma unroll
            for (int e = 0; e < NE; e++) red[e][tid] += red[e][tid + s];
        }
        __syncthreads();
    }
    if (tid == 0) {
        float l[NE], m = -1e30f;
        #pragma unroll
        for (int e = 0; e < NE; e++) { l[e] = red[e][0]; m = fmaxf(m, l[e]); }
        float p[NE], s = 0.f;
        #pragma unroll
        for (int e = 0; e < NE; e++) { p[e] = expf(l[e] - m); s += p[e]; }
        #pragma unroll
        for (int e = 0; e < NE; e++) p[e] /= s;
        int i1 = 0;
        #pragma unroll
        for (int e = 1; e < NE; e++) if (p[e] > p[i1]) i1 = e;
        int i2 = -1; float best = -1.f;
        #pragma unroll
        for (int e = 0; e < NE; e++) if (e != i1 && p[e] > best) { best = p[e]; i2 = e; }
        g_e1[n] = i1; g_e2[n] = i2;
        g_g1[n] = p[i1]; g_g2[n] = p[i2];
    }
}

__global__ void assign1_kernel() {
    int n = blockIdx.x * 256 + threadIdx.x;
    if (n < N_TOK) g_slot1[n] = atomicAdd(&g_cnt1[g_e1[n]], 1);
}

__global__ void assign2_kernel() {
    int n = blockIdx.x * 256 + threadIdx.x;
    if (n >= N_TOK) return;
    int e2 = g_e2[n];
    int off = min(g_cnt1[e2], CAP);
    int s2 = off + atomicAdd(&g_cnt2[e2], 1);
    g_slot2[n] = s2;
    float g1 = (g_slot1[n] < CAP) ? g_g1[n] : 0.f;
    float g2 = (s2 < CAP)         ? g_g2[n] : 0.f;
    float denom = fmaxf(g1 + g2, 1.1920929e-07f);
    g_g1[n] = g1 / denom;
    g_g2[n] = g2 / denom;
}

__global__ void finalize_kernel() {
    int e = threadIdx.x;
    if (e < NE) g_used[e] = min(min(g_cnt1[e], CAP) + g_cnt2[e], CAP);
}

// scatter token into expert buffers (bf16 hi/lo planes)
__global__ void dispatch_kernel(const float* __restrict__ x) {
    int n = blockIdx.x;
    const float4* xr = (const float4*)(x + (size_t)n * H_DIM);
    int e1 = g_e1[n], s1 = g_slot1[n];
    int e2 = g_e2[n], s2 = g_slot2[n];
    size_t r1 = ((size_t)e1 * CAP + s1) * H_DIM;
    size_t r2 = ((size_t)e2 * CAP + s2) * H_DIM;
    uint2* h1 = (s1 < CAP) ? (uint2*)(g_eih + r1) : nullptr;
    uint2* l1 = (s1 < CAP) ? (uint2*)(g_eil + r1) : nullptr;
    uint2* h2 = (s2 < CAP) ? (uint2*)(g_eih + r2) : nullptr;
    uint2* l2 = (s2 < CAP) ? (uint2*)(g_eil + r2) : nullptr;
    for (int i = threadIdx.x; i < H_DIM / 4; i += 256) {
        float4 v = xr[i];
        uint32_t ha, la, hb, lb;
        split2(v.x, v.y, ha, la);
        split2(v.z, v.w, hb, lb);
        uint2 hh = make_uint2(ha, hb), ll = make_uint2(la, lb);
        if (h1) { h1[i] = hh; l1[i] = ll; }
        if (h2) { h2[i] = hh; l2[i] = ll; }
    }
}

__global__ void combine_kernel(float* __restrict__ out) {
    int n = blockIdx.x;
    int e1 = g_e1[n], s1 = g_slot1[n];
    int e2 = g_e2[n], s2 = g_slot2[n];
    float g1 = g_g1[n], g2 = g_g2[n];
    const float4* p1 = (s1 < CAP) ? (const float4*)(g_expert_out + ((size_t)e1 * CAP + s1) * H_DIM) : nullptr;
    const float4* p2 = (s2 < CAP) ? (const float4*)(g_expert_out + ((size_t)e2 * CAP + s2) * H_DIM) : nullptr;
    float4* o = (float4*)(out + (size_t)n * H_DIM);
    for (int i = threadIdx.x; i < H_DIM / 4; i += 256) {
        float4 v = o[i];
        if (p1) { float4 a = p1[i]; v.x += g1 * a.x; v.y += g1 * a.y; v.z += g1 * a.z; v.w += g1 * a.w; }
        if (p2) { float4 a = p2[i]; v.x += g2 * a.x; v.y += g2 * a.y; v.z += g2 * a.z; v.w += g2 * a.w; }
        o[i] = v;
    }
}

// ---------------- launcher ----------------
extern "C" void kernel_launch(void* const* d_in, const int* in_sizes, int n_in,
                              void* d_out, int out_size) {
    const float* x   = (const float*)d_in[0];
    const float* rw  = (const float*)d_in[1];
    const float* w1  = (const float*)d_in[2];
    const float* b1  = (const float*)d_in[3];
    const float* w2  = (const float*)d_in[4];
    const float* b2  = (const float*)d_in[5];
    const float* sw1 = (const float*)d_in[6];
    const float* sb1 = (const float*)d_in[7];
    const float* sw2 = (const float*)d_in[8];
    const float* sb2 = (const float*)d_in[9];
    float* out = (float*)d_out;

    __nv_bfloat16 *w1h, *w1l, *w2h, *w2l, *sw1h, *sw1l, *sw2h, *sw2l;
    __nv_bfloat16 *xh, *xl, *eih, *eil, *hmh, *hml, *smh, *sml;
    float *expert_out;
    int *usedp;
    cudaGetSymbolAddress((void**)&w1h,  g_w1h);  cudaGetSymbolAddress((void**)&w1l,  g_w1l);
    cudaGetSymbolAddress((void**)&w2h,  g_w2h);  cudaGetSymbolAddress((void**)&w2l,  g_w2l);
    cudaGetSymbolAddress((void**)&sw1h, g_sw1h); cudaGetSymbolAddress((void**)&sw1l, g_sw1l);
    cudaGetSymbolAddress((void**)&sw2h, g_sw2h); cudaGetSymbolAddress((void**)&sw2l, g_sw2l);
    cudaGetSymbolAddress((void**)&xh,   g_xh);   cudaGetSymbolAddress((void**)&xl,   g_xl);
    cudaGetSymbolAddress((void**)&eih,  g_eih);  cudaGetSymbolAddress((void**)&eil,  g_eil);
    cudaGetSymbolAddress((void**)&hmh,  g_hmh);  cudaGetSymbolAddress((void**)&hml,  g_hml);
    cudaGetSymbolAddress((void**)&smh,  g_smh);  cudaGetSymbolAddress((void**)&sml,  g_sml);
    cudaGetSymbolAddress((void**)&expert_out, g_expert_out);
    cudaGetSymbolAddress((void**)&usedp, g_used);

    cudaFuncSetAttribute(gemm_tc_kernel, cudaFuncAttributeMaxDynamicSharedMemorySize, SM_TOTAL);

    // preconvert weights + x to bf16 hi/lo (8 elems/thread, exact grid)
    convert_kernel<<<(int)((size_t)NE * H_DIM * F_DIM / 2048), 256>>>((const float4*)w1,  (uint4*)w1h,  (uint4*)w1l);
    convert_kernel<<<(int)((size_t)NE * F_DIM * H_DIM / 2048), 256>>>((const float4*)w2,  (uint4*)w2h,  (uint4*)w2l);
    convert_kernel<<<(int)((size_t)H_DIM * F_DIM / 2048), 256>>>((const float4*)sw1, (uint4*)sw1h, (uint4*)sw1l);
    convert_kernel<<<(int)((size_t)F_DIM * H_DIM / 2048), 256>>>((const float4*)sw2, (uint4*)sw2h, (uint4*)sw2l);
    convert_kernel<<<(int)((size_t)N_TOK * H_DIM / 2048), 256>>>((const float4*)x,   (uint4*)xh,   (uint4*)xl);

    zero_counts_kernel<<<1, 32>>>();
    router_kernel<<<N_TOK, 256>>>(x, rw);
    assign1_kernel<<<N_TOK / 256, 256>>>();
    assign2_kernel<<<N_TOK / 256, 256>>>();
    finalize_kernel<<<1, 32>>>();
    dispatch_kernel<<<N_TOK, 256>>>(x);

    // expert GEMM1: [CAP,H]@[H,F] -> silu -> hmid(bf16)
    {
        dim3 grid(F_DIM / BN, CAP / BM, NE);
        gemm_tc_kernel<<<grid, 256, SM_TOTAL>>>(eih, eil, w1h, w1l, b1,
            nullptr, hmh, hml, F_DIM, H_DIM,
            (long long)CAP * H_DIM, (long long)H_DIM * F_DIM, F_DIM, (long long)CAP * F_DIM,
            1.f, 1, 1, usedp);
    }
    // expert GEMM2: [CAP,F]@[F,H] + b2 -> expert_out(fp32)
    {
        dim3 grid(H_DIM / BN, CAP / BM, NE);
        gemm_tc_kernel<<<grid, 256, SM_TOTAL>>>(hmh, hml, w2h, w2l, b2,
            expert_out, nullptr, nullptr, H_DIM, F_DIM,
            (long long)CAP * F_DIM, (long long)F_DIM * H_DIM, H_DIM, (long long)CAP * H_DIM,
            1.f, 0, 0, usedp);
    }
    // shared GEMM3: [N,H]@[H,F] -> silu -> smid(bf16)
    {
        dim3 grid(F_DIM / BN, N_TOK / BM, 1);
        gemm_tc_kernel<<<grid, 256, SM_TOTAL>>>(xh, xl, sw1h, sw1l, sb1,
            nullptr, smh, sml, F_DIM, H_DIM,
            0, 0, 0, 0, 1.f, 1, 1, nullptr);
    }
    // shared GEMM4: 0.1 * ([N,F]@[F,H] + sb2) -> out(fp32)
    {
        dim3 grid(H_DIM / BN, N_TOK / BM, 1);
        gemm_tc_kernel<<<grid, 256, SM_TOTAL>>>(smh, sml, sw2h, sw2l, sb2,
            out, nullptr, nullptr, H_DIM, F_DIM,
            0, 0, 0, 0, 0.1f, 0, 0, nullptr);
    }
    combine_kernel<<<N_TOK, 256>>>(out);
}

// round 6
// speedup vs baseline: 2.8446x; 1.0232x over previous
#include <cuda_runtime.h>
#include <cuda_bf16.h>
#include <math.h>
#include <stdint.h>

#define N_TOK 4096
#define H_DIM 1024
#define F_DIM 4096
#define NE 8
#define CAP 1280   // min(max(4, ceil(2*1.25*4096/8)), 4096)

// ---------------- scratch (device globals; no allocations allowed) ----------------
__device__ __nv_bfloat16 g_w1h[(size_t)NE * H_DIM * F_DIM], g_w1l[(size_t)NE * H_DIM * F_DIM];
__device__ __nv_bfloat16 g_w2h[(size_t)NE * F_DIM * H_DIM], g_w2l[(size_t)NE * F_DIM * H_DIM];
__device__ __nv_bfloat16 g_sw1h[(size_t)H_DIM * F_DIM],     g_sw1l[(size_t)H_DIM * F_DIM];
__device__ __nv_bfloat16 g_sw2h[(size_t)F_DIM * H_DIM],     g_sw2l[(size_t)F_DIM * H_DIM];
__device__ __nv_bfloat16 g_xh [(size_t)N_TOK * H_DIM],      g_xl [(size_t)N_TOK * H_DIM];
__device__ __nv_bfloat16 g_eih[(size_t)NE * CAP * H_DIM],   g_eil[(size_t)NE * CAP * H_DIM];
__device__ __nv_bfloat16 g_hmh[(size_t)NE * CAP * F_DIM],   g_hml[(size_t)NE * CAP * F_DIM];
__device__ __nv_bfloat16 g_smh[(size_t)N_TOK * F_DIM],      g_sml[(size_t)N_TOK * F_DIM];
__device__ float g_expert_out[(size_t)NE * CAP * H_DIM];
__device__ int   g_e1[N_TOK];
__device__ int   g_e2[N_TOK];
__device__ int   g_slot1[N_TOK];
__device__ int   g_slot2[N_TOK];
__device__ float g_g1[N_TOK];
__device__ float g_g2[N_TOK];
__device__ int   g_cnt1[NE];
__device__ int   g_cnt2[NE];
__device__ int   g_used[NE];

// ---------------- helpers ----------------
__device__ __forceinline__ uint32_t smem_u32(const void* p) {
    uint32_t a;
    asm("{ .reg .u64 t; cvta.to.shared.u64 t, %1; cvt.u32.u64 %0, t; }" : "=r"(a) : "l"(p));
    return a;
}
#define LDSM_X4(r0, r1, r2, r3, addr) \
    asm volatile("ldmatrix.sync.aligned.m8n8.x4.shared.b16 {%0,%1,%2,%3}, [%4];" \
        : "=r"(r0), "=r"(r1), "=r"(r2), "=r"(r3) : "r"(addr))
#define LDSM_X4T(r0, r1, r2, r3, addr) \
    asm volatile("ldmatrix.sync.aligned.m8n8.x4.trans.shared.b16 {%0,%1,%2,%3}, [%4];" \
        : "=r"(r0), "=r"(r1), "=r"(r2), "=r"(r3) : "r"(addr))
__device__ __forceinline__ void mma16816(float* d, const uint32_t* a, const uint32_t* b) {
    asm volatile(
        "mma.sync.aligned.m16n8k16.row.col.f32.bf16.bf16.f32 "
        "{%0,%1,%2,%3}, {%4,%5,%6,%7}, {%8,%9}, {%0,%1,%2,%3};"
        : "+f"(d[0]), "+f"(d[1]), "+f"(d[2]), "+f"(d[3])
        : "r"(a[0]), "r"(a[1]), "r"(a[2]), "r"(a[3]), "r"(b[0]), "r"(b[1]));
}
__device__ __forceinline__ void cp16(uint32_t dst, const void* src) {
    asm volatile("cp.async.cg.shared.global [%0], [%1], 16;" :: "r"(dst), "l"(src));
}
#define CP_COMMIT() asm volatile("cp.async.commit_group;" ::: "memory")
#define CP_WAIT2()  asm volatile("cp.async.wait_group 2;" ::: "memory")

// split fp32 pair -> packed bf16x2 hi and lo (residual)
__device__ __forceinline__ void split2(float a, float b, uint32_t& hi, uint32_t& lo) {
    __nv_bfloat16 ha = __float2bfloat16_rn(a), hb = __float2bfloat16_rn(b);
    float ra = a - __bfloat162float(ha);
    float rb = b - __bfloat162float(hb);
    unsigned short ua = *reinterpret_cast<unsigned short*>(&ha);
    unsigned short ub = *reinterpret_cast<unsigned short*>(&hb);
    hi = (uint32_t)ua | ((uint32_t)ub << 16);
    __nv_bfloat16 la = __float2bfloat16_rn(ra), lb = __float2bfloat16_rn(rb);
    unsigned short va = *reinterpret_cast<unsigned short*>(&la);
    unsigned short vb = *reinterpret_cast<unsigned short*>(&lb);
    lo = (uint32_t)va | ((uint32_t)vb << 16);
}

// fp32 -> bf16 hi/lo planes: 16 elems per thread, exact grid
__global__ __launch_bounds__(256) void convert_kernel(
    const float4* __restrict__ in, uint4* __restrict__ hi, uint4* __restrict__ lo) {
    int i = blockIdx.x * 256 + threadIdx.x;
    float4 v0 = in[i * 4 + 0], v1 = in[i * 4 + 1], v2 = in[i * 4 + 2], v3 = in[i * 4 + 3];
    uint4 h0, l0, h1, l1;
    split2(v0.x, v0.y, h0.x, l0.x);
    split2(v0.z, v0.w, h0.y, l0.y);
    split2(v1.x, v1.y, h0.z, l0.z);
    split2(v1.z, v1.w, h0.w, l0.w);
    split2(v2.x, v2.y, h1.x, l1.x);
    split2(v2.z, v2.w, h1.y, l1.y);
    split2(v3.x, v3.y, h1.z, l1.z);
    split2(v3.z, v3.w, h1.w, l1.w);
    hi[i * 2] = h0; hi[i * 2 + 1] = h1;
    lo[i * 2] = l0; lo[i * 2 + 1] = l1;
}

// ---------------- GEMM tiling ----------------
#define BM 128
#define BN 128
#define BK 32
#define A_PITCH_B 80
#define B_PITCH_B 272
#define SA_BYTES (BM * A_PITCH_B)            // 10240
#define SB_BYTES (BK * B_PITCH_B)            // 8704
#define OFF_A_HI 0
#define OFF_A_LO SA_BYTES
#define OFF_B_HI (2 * SA_BYTES)
#define OFF_B_LO (2 * SA_BYTES + SB_BYTES)
#define STAGE_BYTES (2 * SA_BYTES + 2 * SB_BYTES)   // 37888
#define NSTAGE 4
#define SM_TOTAL (NSTAGE * STAGE_BYTES)             // 151552

// ---------------- bf16x3 warp-MMA GEMM core (cp.async pipeline) ----------------
template<int ACT, int OUT_BF16>
__device__ __forceinline__ void gemm_core(
    const __nv_bfloat16* __restrict__ Ahi, const __nv_bfloat16* __restrict__ Alo,
    const __nv_bfloat16* __restrict__ Bhi, const __nv_bfloat16* __restrict__ Blo,
    const float* __restrict__ bias,
    float* __restrict__ Cf, __nv_bfloat16* __restrict__ Chi, __nv_bfloat16* __restrict__ Clo,
    int Ncol, int K, int bm, int bn, float alpha)
{
    extern __shared__ char smem[];
    const int tid = threadIdx.x, w = tid >> 5, lane = tid & 31;
    const uint32_t sbase = smem_u32(smem);
    const int wm = (w >> 2) * 64, wn = (w & 3) * 32;

    const int ra0 = tid >> 2, ca = (tid & 3);
    const int rb0 = tid >> 4, cb = (tid & 15);
    const uint32_t a_dst0 = (uint32_t)ra0 * A_PITCH_B + (uint32_t)ca * 16;
    const uint32_t b_dst0 = (uint32_t)rb0 * B_PITCH_B + (uint32_t)cb * 16;
    const __nv_bfloat16* aSh0 = Ahi + (size_t)(bm + ra0) * K + ca * 8;
    const __nv_bfloat16* aSl0 = Alo + (size_t)(bm + ra0) * K + ca * 8;
    const __nv_bfloat16* aSh1 = aSh0 + (size_t)64 * K;
    const __nv_bfloat16* aSl1 = aSl0 + (size_t)64 * K;
    const __nv_bfloat16* bSh0 = Bhi + (size_t)rb0 * Ncol + bn + cb * 8;
    const __nv_bfloat16* bSl0 = Blo + (size_t)rb0 * Ncol + bn + cb * 8;
    const __nv_bfloat16* bSh1 = bSh0 + (size_t)16 * Ncol;
    const __nv_bfloat16* bSl1 = bSl0 + (size_t)16 * Ncol;

    const uint32_t aoff = (uint32_t)(wm + (lane & 15)) * A_PITCH_B + ((lane >> 4) ? 16u : 0u);
    const uint32_t boff = (uint32_t)(lane & 15) * B_PITCH_B + (uint32_t)(wn + (lane >> 4) * 8) * 2;

    float acc[4][4][4];
    #pragma unroll
    for (int i = 0; i < 4; i++)
        #pragma unroll
        for (int j = 0; j < 4; j++)
            #pragma unroll
            for (int kq = 0; kq < 4; kq++) acc[i][j][kq] = 0.f;

    const int S = K / BK;

    #pragma unroll
    for (int s = 0; s < NSTAGE - 1; s++) {
        const uint32_t stb = sbase + (uint32_t)s * STAGE_BYTES;
        const int k0 = s * BK;
        cp16(stb + OFF_A_HI + a_dst0,                  aSh0 + k0);
        cp16(stb + OFF_A_HI + a_dst0 + 64 * A_PITCH_B, aSh1 + k0);
        cp16(stb + OFF_A_LO + a_dst0,                  aSl0 + k0);
        cp16(stb + OFF_A_LO + a_dst0 + 64 * A_PITCH_B, aSl1 + k0);
        cp16(stb + OFF_B_HI + b_dst0,                  bSh0 + (size_t)k0 * Ncol);
        cp16(stb + OFF_B_HI + b_dst0 + 16 * B_PITCH_B, bSh1 + (size_t)k0 * Ncol);
        cp16(stb + OFF_B_LO + b_dst0,                  bSl0 + (size_t)k0 * Ncol);
        cp16(stb + OFF_B_LO + b_dst0 + 16 * B_PITCH_B, bSl1 + (size_t)k0 * Ncol);
        CP_COMMIT();
    }

    for (int s = 0; s < S; s++) {
        CP_WAIT2();
        __syncthreads();
        if (s + NSTAGE - 1 < S) {
            const uint32_t stb = sbase + (uint32_t)((s + NSTAGE - 1) & (NSTAGE - 1)) * STAGE_BYTES;
            const int k0 = (s + NSTAGE - 1) * BK;
            cp16(stb + OFF_A_HI + a_dst0,                  aSh0 + k0);
            cp16(stb + OFF_A_HI + a_dst0 + 64 * A_PITCH_B, aSh1 + k0);
            cp16(stb + OFF_A_LO + a_dst0,                  aSl0 + k0);
            cp16(stb + OFF_A_LO + a_dst0 + 64 * A_PITCH_B, aSl1 + k0);
            cp16(stb + OFF_B_HI + b_dst0,                  bSh0 + (size_t)k0 * Ncol);
            cp16(stb + OFF_B_HI + b_dst0 + 16 * B_PITCH_B, bSh1 + (size_t)k0 * Ncol);
            cp16(stb + OFF_B_LO + b_dst0,                  bSl0 + (size_t)k0 * Ncol);
            cp16(stb + OFF_B_LO + b_dst0 + 16 * B_PITCH_B, bSl1 + (size_t)k0 * Ncol);
        }
        CP_COMMIT();
        const uint32_t stb = sbase + (uint32_t)(s & (NSTAGE - 1)) * STAGE_BYTES;
        #pragma unroll
        for (int ks = 0; ks < 2; ks++) {
            const int kb = ks * 16;
            uint32_t ah[4][4], al[4][4];
            #pragma unroll
            for (int mt = 0; mt < 4; mt++) {
                uint32_t ad = stb + aoff + (uint32_t)mt * (16 * A_PITCH_B) + (uint32_t)kb * 2;
                LDSM_X4(ah[mt][0], ah[mt][1], ah[mt][2], ah[mt][3], ad + OFF_A_HI);
                LDSM_X4(al[mt][0], al[mt][1], al[mt][2], al[mt][3], ad + OFF_A_LO);
            }
            uint32_t bh[2][4], bl[2][4];
            #pragma unroll
            for (int np = 0; np < 2; np++) {
                uint32_t bd = stb + boff + (uint32_t)kb * B_PITCH_B + (uint32_t)np * 32;
                LDSM_X4T(bh[np][0], bh[np][1], bh[np][2], bh[np][3], bd + OFF_B_HI);
                LDSM_X4T(bl[np][0], bl[np][1], bl[np][2], bl[np][3], bd + OFF_B_LO);
            }
            #pragma unroll
            for (int mt = 0; mt < 4; mt++) {
                #pragma unroll
                for (int nt = 0; nt < 4; nt++) {
                    uint32_t* ph = &bh[nt >> 1][(nt & 1) * 2];
                    uint32_t* pl = &bl[nt >> 1][(nt & 1) * 2];
                    mma16816(acc[mt][nt], ah[mt], ph);
                    mma16816(acc[mt][nt], ah[mt], pl);
                    mma16816(acc[mt][nt], al[mt], ph);
                }
            }
        }
    }

    // --- epilogue ---
    const int lr = lane >> 2, lc = (lane & 3) * 2;
    #pragma unroll
    for (int mt = 0; mt < 4; mt++) {
        #pragma unroll
        for (int nt = 0; nt < 4; nt++) {
            int col = bn + wn + nt * 8 + lc;
            float b0 = bias[col], b1 = bias[col + 1];
            #pragma unroll
            for (int half = 0; half < 2; half++) {
                long long row = bm + wm + mt * 16 + lr + half * 8;
                float vx = acc[mt][nt][half * 2 + 0] + b0;
                float vy = acc[mt][nt][half * 2 + 1] + b1;
                if (ACT) {
                    vx = vx / (1.f + expf(-vx));
                    vy = vy / (1.f + expf(-vy));
                }
                vx *= alpha; vy *= alpha;
                if (OUT_BF16) {
                    uint32_t h, l;
                    split2(vx, vy, h, l);
                    *(uint32_t*)(Chi + row * Ncol + col) = h;
                    *(uint32_t*)(Clo + row * Ncol + col) = l;
                } else {
                    *(float2*)(Cf + row * Ncol + col) = make_float2(vx, vy);
                }
            }
        }
    }
}

// merged GEMM stage 1: experts (z<8) and shared (z>=8), [*,1024]@[1024,4096] -> silu -> bf16
// grid: (F/128, 10, 12)
__global__ __launch_bounds__(256, 1) void gemm1_kernel(
    const float* __restrict__ b1, const float* __restrict__ sb1)
{
    const int z = blockIdx.z;
    const __nv_bfloat16 *Ahi, *Alo, *Bhi, *Blo;
    __nv_bfloat16 *Chi, *Clo;
    const float* bias;
    int bm;
    if (z < NE) {
        bm = blockIdx.y * BM;
        if (bm >= g_used[z]) return;
        Ahi = g_eih + (size_t)z * CAP * H_DIM;  Alo = g_eil + (size_t)z * CAP * H_DIM;
        Bhi = g_w1h + (size_t)z * H_DIM * F_DIM; Blo = g_w1l + (size_t)z * H_DIM * F_DIM;
        bias = b1 + (size_t)z * F_DIM;
        Chi = g_hmh + (size_t)z * CAP * F_DIM;  Clo = g_hml + (size_t)z * CAP * F_DIM;
    } else {
        int t = (z - NE) * gridDim.y + blockIdx.y;
        if (t >= N_TOK / BM) return;
        bm = t * BM;
        Ahi = g_xh;  Alo = g_xl;
        Bhi = g_sw1h; Blo = g_sw1l;
        bias = sb1;
        Chi = g_smh; Clo = g_sml;
    }
    gemm_core<1, 1>(Ahi, Alo, Bhi, Blo, bias, nullptr, Chi, Clo,
                    F_DIM, H_DIM, bm, blockIdx.x * BN, 1.f);
}

// merged GEMM stage 2: [*,4096]@[4096,1024] + bias -> fp32 (experts -> expert_out, shared -> 0.1*out)
// grid: (H/128, 10, 12)
__global__ __launch_bounds__(256, 1) void gemm2_kernel(
    const float* __restrict__ b2, const float* __restrict__ sb2, float* __restrict__ out)
{
    const int z = blockIdx.z;
    const __nv_bfloat16 *Ahi, *Alo, *Bhi, *Blo;
    float* Cf;
    const float* bias;
    int bm;
    float alpha;
    if (z < NE) {
        bm = blockIdx.y * BM;
        if (bm >= g_used[z]) return;
        Ahi = g_hmh + (size_t)z * CAP * F_DIM;  Alo = g_hml + (size_t)z * CAP * F_DIM;
        Bhi = g_w2h + (size_t)z * F_DIM * H_DIM; Blo = g_w2l + (size_t)z * F_DIM * H_DIM;
        bias = b2 + (size_t)z * H_DIM;
        Cf = g_expert_out + (size_t)z * CAP * H_DIM;
        alpha = 1.f;
    } else {
        int t = (z - NE) * gridDim.y + blockIdx.y;
        if (t >= N_TOK / BM) return;
        bm = t * BM;
        Ahi = g_smh; Alo = g_sml;
        Bhi = g_sw2h; Blo = g_sw2l;
        bias = sb2;
        Cf = out;
        alpha = 0.1f;
    }
    gemm_core<0, 0>(Ahi, Alo, Bhi, Blo, bias, Cf, nullptr, nullptr,
                    H_DIM, F_DIM, bm, blockIdx.x * BN, alpha);
}

// ---------------- routing ----------------
__global__ void zero_counts_kernel() {
    int t = threadIdx.x;
    if (t < NE) { g_cnt1[t] = 0; g_cnt2[t] = 0; }
}

__global__ void router_kernel(const float* __restrict__ x, const float* __restrict__ rw) {
    int n = blockIdx.x;
    int tid = threadIdx.x;
    float acc[NE];
    #pragma unroll
    for (int e = 0; e < NE; e++) acc[e] = 0.f;
    const float* xr = x + (size_t)n * H_DIM;
    for (int h = tid; h < H_DIM; h += 256) {
        float xv = xr[h];
        const float* r = rw + h * NE;
        #pragma unroll
        for (int e = 0; e < NE; e++) acc[e] += xv * r[e];
    }
    __shared__ float red[NE][256];
    #pragma unroll
    for (int e = 0; e < NE; e++) red[e][tid] = acc[e];
    __syncthreads();
    for (int s = 128; s > 0; s >>= 1) {
        if (tid < s) {
            #pragma unroll
            for (int e = 0; e < NE; e++) red[e][tid] += red[e][tid + s];
        }
        __syncthreads();
    }
    if (tid == 0) {
        float l[NE], m = -1e30f;
        #pragma unroll
        for (int e = 0; e < NE; e++) { l[e] = red[e][0]; m = fmaxf(m, l[e]); }
        float p[NE], s = 0.f;
        #pragma unroll
        for (int e = 0; e < NE; e++) { p[e] = expf(l[e] - m); s += p[e]; }
        #pragma unroll
        for (int e = 0; e < NE; e++) p[e] /= s;
        int i1 = 0;
        #pragma unroll
        for (int e = 1; e < NE; e++) if (p[e] > p[i1]) i1 = e;
        int i2 = -1; float best = -1.f;
        #pragma unroll
        for (int e = 0; e < NE; e++) if (e != i1 && p[e] > best) { best = p[e]; i2 = e; }
        g_e1[n] = i1; g_e2[n] = i2;
        g_g1[n] = p[i1]; g_g2[n] = p[i2];
    }
}

__global__ void assign1_kernel() {
    int n = blockIdx.x * 256 + threadIdx.x;
    if (n < N_TOK) g_slot1[n] = atomicAdd(&g_cnt1[g_e1[n]], 1);
}

__global__ void assign2_kernel() {
    int n = blockIdx.x * 256 + threadIdx.x;
    if (n >= N_TOK) return;
    int e2 = g_e2[n];
    int off = min(g_cnt1[e2], CAP);
    int s2 = off + atomicAdd(&g_cnt2[e2], 1);
    g_slot2[n] = s2;
    float g1 = (g_slot1[n] < CAP) ? g_g1[n] : 0.f;
    float g2 = (s2 < CAP)         ? g_g2[n] : 0.f;
    float denom = fmaxf(g1 + g2, 1.1920929e-07f);
    g_g1[n] = g1 / denom;
    g_g2[n] = g2 / denom;
}

__global__ void finalize_kernel() {
    int e = threadIdx.x;
    if (e < NE) g_used[e] = min(min(g_cnt1[e], CAP) + g_cnt2[e], CAP);
}

// scatter token into expert buffers (bf16 hi/lo planes)
__global__ void dispatch_kernel(const float* __restrict__ x) {
    int n = blockIdx.x;
    const float4* xr = (const float4*)(x + (size_t)n * H_DIM);
    int e1 = g_e1[n], s1 = g_slot1[n];
    int e2 = g_e2[n], s2 = g_slot2[n];
    size_t r1 = ((size_t)e1 * CAP + s1) * H_DIM;
    size_t r2 = ((size_t)e2 * CAP + s2) * H_DIM;
    uint2* h1 = (s1 < CAP) ? (uint2*)(g_eih + r1) : nullptr;
    uint2* l1 = (s1 < CAP) ? (uint2*)(g_eil + r1) : nullptr;
    uint2* h2 = (s2 < CAP) ? (uint2*)(g_eih + r2) : nullptr;
    uint2* l2 = (s2 < CAP) ? (uint2*)(g_eil + r2) : nullptr;
    for (int i = threadIdx.x; i < H_DIM / 4; i += 256) {
        float4 v = xr[i];
        uint32_t ha, la, hb, lb;
        split2(v.x, v.y, ha, la);
        split2(v.z, v.w, hb, lb);
        uint2 hh = make_uint2(ha, hb), ll = make_uint2(la, lb);
        if (h1) { h1[i] = hh; l1[i] = ll; }
        if (h2) { h2[i] = hh; l2[i] = ll; }
    }
}

__global__ void combine_kernel(float* __restrict__ out) {
    int n = blockIdx.x;
    int e1 = g_e1[n], s1 = g_slot1[n];
    int e2 = g_e2[n], s2 = g_slot2[n];
    float g1 = g_g1[n], g2 = g_g2[n];
    const float4* p1 = (s1 < CAP) ? (const float4*)(g_expert_out + ((size_t)e1 * CAP + s1) * H_DIM) : nullptr;
    const float4* p2 = (s2 < CAP) ? (const float4*)(g_expert_out + ((size_t)e2 * CAP + s2) * H_DIM) : nullptr;
    float4* o = (float4*)(out + (size_t)n * H_DIM);
    for (int i = threadIdx.x; i < H_DIM / 4; i += 256) {
        float4 v = o[i];
        if (p1) { float4 a = p1[i]; v.x += g1 * a.x; v.y += g1 * a.y; v.z += g1 * a.z; v.w += g1 * a.w; }
        if (p2) { float4 a = p2[i]; v.x += g2 * a.x; v.y += g2 * a.y; v.z += g2 * a.z; v.w += g2 * a.w; }
        o[i] = v;
    }
}

// ---------------- launcher ----------------
extern "C" void kernel_launch(void* const* d_in, const int* in_sizes, int n_in,
                              void* d_out, int out_size) {
    const float* x   = (const float*)d_in[0];
    const float* rw  = (const float*)d_in[1];
    const float* w1  = (const float*)d_in[2];
    const float* b1  = (const float*)d_in[3];
    const float* w2  = (const float*)d_in[4];
    const float* b2  = (const float*)d_in[5];
    const float* sw1 = (const float*)d_in[6];
    const float* sb1 = (const float*)d_in[7];
    const float* sw2 = (const float*)d_in[8];
    const float* sb2 = (const float*)d_in[9];
    float* out = (float*)d_out;

    __nv_bfloat16 *w1h, *w1l, *w2h, *w2l, *sw1h, *sw1l, *sw2h, *sw2l, *xh, *xl;
    cudaGetSymbolAddress((void**)&w1h,  g_w1h);  cudaGetSymbolAddress((void**)&w1l,  g_w1l);
    cudaGetSymbolAddress((void**)&w2h,  g_w2h);  cudaGetSymbolAddress((void**)&w2l,  g_w2l);
    cudaGetSymbolAddress((void**)&sw1h, g_sw1h); cudaGetSymbolAddress((void**)&sw1l, g_sw1l);
    cudaGetSymbolAddress((void**)&sw2h, g_sw2h); cudaGetSymbolAddress((void**)&sw2l, g_sw2l);
    cudaGetSymbolAddress((void**)&xh,   g_xh);   cudaGetSymbolAddress((void**)&xl,   g_xl);

    cudaFuncSetAttribute(gemm1_kernel, cudaFuncAttributeMaxDynamicSharedMemorySize, SM_TOTAL);
    cudaFuncSetAttribute(gemm2_kernel, cudaFuncAttributeMaxDynamicSharedMemorySize, SM_TOTAL);

    // preconvert weights + x to bf16 hi/lo (16 elems/thread, exact grid)
    convert_kernel<<<(int)((size_t)NE * H_DIM * F_DIM / 4096), 256>>>((const float4*)w1,  (uint4*)w1h,  (uint4*)w1l);
    convert_kernel<<<(int)((size_t)NE * F_DIM * H_DIM / 4096), 256>>>((const float4*)w2,  (uint4*)w2h,  (uint4*)w2l);
    convert_kernel<<<(int)((size_t)H_DIM * F_DIM / 4096), 256>>>((const float4*)sw1, (uint4*)sw1h, (uint4*)sw1l);
    convert_kernel<<<(int)((size_t)F_DIM * H_DIM / 4096), 256>>>((const float4*)sw2, (uint4*)sw2h, (uint4*)sw2l);
    convert_kernel<<<(int)((size_t)N_TOK * H_DIM / 4096), 256>>>((const float4*)x,   (uint4*)xh,   (uint4*)xl);

    zero_counts_kernel<<<1, 32>>>();
    router_kernel<<<N_TOK, 256>>>(x, rw);
    assign1_kernel<<<N_TOK / 256, 256>>>();
    assign2_kernel<<<N_TOK / 256, 256>>>();
    finalize_kernel<<<1, 32>>>();
    dispatch_kernel<<<N_TOK, 256>>>(x);

    // merged stage 1: experts + shared  (z in [0,12))
    {
        dim3 grid(F_DIM / BN, CAP / BM, NE + 4);
        gemm1_kernel<<<grid, 256, SM_TOTAL>>>(b1, sb1);
    }
    // merged stage 2: experts + shared
    {
        dim3 grid(H_DIM / BN, CAP / BM, NE + 4);
        gemm2_kernel<<<grid, 256, SM_TOTAL>>>(b2, sb2, out);
    }
    combine_kernel<<<N_TOK, 256>>>(out);
}